// round 10
// baseline (speedup 1.0000x reference)
#include <cuda_runtime.h>
#include <cuda_bf16.h>
#include <cstdint>
#include <math.h>

#define BB 8
#define TT 32
#define NN 1024
#define DIN 64
#define DR 128
#define DT_C 0.25f
typedef __nv_bfloat16 bf16;

// weight arena element offsets
#define OW0 0
#define OW1 16384
#define OWOUT 32768
#define OWZ 49152
#define OWR 73728
#define OWH 98304
#define OWO 122880

// ------------------------- device scratch (no allocs) ----------------------
__device__ bf16 g_Ahi[(size_t)BB*NN*NN];
__device__ bf16 g_Alo[(size_t)BB*NN*NN];
__device__ bf16 g_Xhi[(size_t)BB*TT*NN*DIN];
__device__ bf16 g_Xlo[(size_t)BB*TT*NN*DIN];
__device__ bf16 g_AXhi[(size_t)TT*BB*NN*DIN];
__device__ bf16 g_AXlo[(size_t)TT*BB*NN*DIN];
__device__ float g_H[BB*NN*DR];
__device__ bf16 g_Hhi[BB*NN*DR], g_Hlo[BB*NN*DR];
__device__ float g_HV1[BB*NN*DR];
__device__ bf16 g_HV1hi[BB*NN*DR], g_HV1lo[BB*NN*DR];
__device__ bf16 g_Uhi[BB*NN*DR], g_Ulo[BB*NN*DR];
__device__ bf16 g_RHhi[BB*NN*DR], g_RHlo[BB*NN*DR];
__device__ float g_Z[BB*NN*DR];
__device__ float g_OBS[TT*BB];
__device__ bf16 g_Whi[131072], g_Wlo[131072];

struct EpiArgs {
    int emode, t;            // 0 AX, 1 tanh->U, 2 hv1(+head), 3 Z&RH, 4 Hblend
    long w1, w2;
    const float *b1, *b2;
    float* of32;
    bf16 *ohi, *olo;
    float* dout;
};

// ----------------------------- PTX helpers ---------------------------------
__device__ __forceinline__ unsigned smem_u32(const void* p) {
    unsigned a;
    asm("{ .reg .u64 t; cvta.to.shared.u64 t, %1; cvt.u32.u64 %0, t; }"
        : "=r"(a) : "l"(p));
    return a;
}
__device__ __forceinline__ void ldm_x4(unsigned& r0, unsigned& r1,
                                       unsigned& r2, unsigned& r3, unsigned a) {
    asm volatile("ldmatrix.sync.aligned.m8n8.x4.shared.b16 {%0,%1,%2,%3}, [%4];"
                 : "=r"(r0), "=r"(r1), "=r"(r2), "=r"(r3) : "r"(a));
}
__device__ __forceinline__ void ldm_x2t(unsigned& r0, unsigned& r1, unsigned a) {
    asm volatile("ldmatrix.sync.aligned.m8n8.x2.trans.shared.b16 {%0,%1}, [%2];"
                 : "=r"(r0), "=r"(r1) : "r"(a));
}
__device__ __forceinline__ void ldm_x4t(unsigned& r0, unsigned& r1,
                                        unsigned& r2, unsigned& r3, unsigned a) {
    asm volatile("ldmatrix.sync.aligned.m8n8.x4.trans.shared.b16 {%0,%1,%2,%3}, [%4];"
                 : "=r"(r0), "=r"(r1), "=r"(r2), "=r"(r3) : "r"(a));
}
__device__ __forceinline__ void mma_bf16(float* c, const unsigned* A, const unsigned* B) {
    asm volatile(
        "mma.sync.aligned.m16n8k16.row.col.f32.bf16.bf16.f32 "
        "{%0,%1,%2,%3}, {%4,%5,%6,%7}, {%8,%9}, {%0,%1,%2,%3};"
        : "+f"(c[0]), "+f"(c[1]), "+f"(c[2]), "+f"(c[3])
        : "r"(A[0]), "r"(A[1]), "r"(A[2]), "r"(A[3]), "r"(B[0]), "r"(B[1]));
}
__device__ __forceinline__ void cp16(unsigned s, const void* g) {
    asm volatile("cp.async.cg.shared.global [%0], [%1], 16;" :: "r"(s), "l"(g));
}
__device__ __forceinline__ void cp_commit() { asm volatile("cp.async.commit_group;"); }
template<int N> __device__ __forceinline__ void cp_wait() {
    asm volatile("cp.async.wait_group %0;" :: "n"(N));
}
__device__ __forceinline__ void store_hilo(bf16* hi, bf16* lo, size_t idx,
                                           float a, float b) {
    __nv_bfloat162 h = __floats2bfloat162_rn(a, b);
    *(unsigned*)(hi + idx) = *reinterpret_cast<unsigned*>(&h);
    __nv_bfloat162 l = __floats2bfloat162_rn(a - __bfloat162float(h.x),
                                             b - __bfloat162float(h.y));
    *(unsigned*)(lo + idx) = *reinterpret_cast<unsigned*>(&l);
}
__device__ __forceinline__ float sigm(float x) { return 1.f / (1.f + expf(-x)); }

// epilogue smem layout (elements)
#define AP2 200
#define ACT_LO 12800              // 64*AP2
#define WBOFF 25600               // 2*64*AP2

// epilogue GEMM: act tile (smem) x W chunk -> e[2][NBE][4]; 256 threads
template<int NBE>
__device__ __forceinline__ void epi_gemm(
    bf16* sm, unsigned sbase, int Kd, int WP,
    const bf16* Whi, const bf16* Wlo, int Dout,
    int tid, int lane, int m0w, int n0e, float (&e)[2][NBE][4])
{
    #pragma unroll
    for (int i = 0; i < 2; i++)
        #pragma unroll
        for (int j = 0; j < NBE; j++)
            #pragma unroll
            for (int q = 0; q < 4; q++) e[i][j][q] = 0.f;
    const int wlo = WBOFF + 64 * WP;
    for (int k0 = 0; k0 < Kd; k0 += 64) {
        __syncthreads();
        const int du4 = Dout / 8;
        for (int it = tid; it < 64 * du4; it += 256) {
            int r = it / du4, c = (it % du4) * 8;
            cp16(sbase + 2u * (WBOFF + r * WP + c),
                 Whi + (size_t)(k0 + r) * Dout + c);
            cp16(sbase + 2u * (wlo + r * WP + c),
                 Wlo + (size_t)(k0 + r) * Dout + c);
        }
        cp_commit();
        cp_wait<0>();
        __syncthreads();
        #pragma unroll
        for (int ks = 0; ks < 4; ks++) {
            const int kk = ks * 16;
            unsigned ah[2][4], al[2][4];
            #pragma unroll
            for (int mi = 0; mi < 2; mi++) {
                unsigned row = m0w + mi * 16 + (lane & 15);
                unsigned col = k0 + kk + (lane >> 4) * 8;
                ldm_x4(ah[mi][0], ah[mi][1], ah[mi][2], ah[mi][3],
                       sbase + 2u * (row * AP2 + col));
                ldm_x4(al[mi][0], al[mi][1], al[mi][2], al[mi][3],
                       sbase + 2u * (ACT_LO + row * AP2 + col));
            }
            unsigned bh[NBE][2], bl[NBE][2];
            if constexpr (NBE >= 2) {
                #pragma unroll
                for (int ni = 0; ni < NBE; ni += 2) {
                    unsigned row = kk + (lane & 15);
                    unsigned col = n0e + ni * 8 + (lane >> 4) * 8;
                    ldm_x4t(bh[ni][0], bh[ni][1], bh[ni+1][0], bh[ni+1][1],
                            sbase + 2u * (WBOFF + row * WP + col));
                    ldm_x4t(bl[ni][0], bl[ni][1], bl[ni+1][0], bl[ni+1][1],
                            sbase + 2u * (wlo + row * WP + col));
                }
            } else {
                unsigned row = kk + (lane & 15);
                ldm_x2t(bh[0][0], bh[0][1], sbase + 2u * (WBOFF + row * WP + n0e));
                ldm_x2t(bl[0][0], bl[0][1], sbase + 2u * (wlo + row * WP + n0e));
            }
            #pragma unroll
            for (int mi = 0; mi < 2; mi++)
                #pragma unroll
                for (int ni = 0; ni < NBE; ni++) {
                    mma_bf16(e[mi][ni], ah[mi], bh[ni]);
                    mma_bf16(e[mi][ni], ah[mi], bl[ni]);
                    mma_bf16(e[mi][ni], al[mi], bh[ni]);
                }
        }
    }
}

template<int NBX>
__device__ __forceinline__ void frag2act(const float (&a)[2][NBX][4], bf16* sm,
                                         int goff, int m0, int n0, int lane)
{
    const int g4 = lane >> 2, t4 = lane & 3;
    #pragma unroll
    for (int mi = 0; mi < 2; mi++)
        #pragma unroll
        for (int ni = 0; ni < NBX; ni++) {
            int r0 = m0 + mi * 16 + g4;
            int c  = goff + n0 + ni * 8 + t4 * 2;
            store_hilo(sm, sm + ACT_LO, (size_t)r0 * AP2 + c,
                       a[mi][ni][0], a[mi][ni][1]);
            store_hilo(sm, sm + ACT_LO, (size_t)(r0 + 8) * AP2 + c,
                       a[mi][ni][2], a[mi][ni][3]);
        }
}

// ---------------------------------------------------------------------------
// agT: C = A[z] @ B[z] (M=K=1024, N=DN) + fused epilogue (DN=128).
// 256 threads (8 warps: 2m x 4n), 2-stage cp.async (fits 2 CTAs/SM),
// one barrier per chunk.
// ---------------------------------------------------------------------------
template<int DN>
__global__ void __launch_bounds__(256, 2) agT_kernel(
    const bf16* __restrict__ Bhi_g, const bf16* __restrict__ Blo_g,
    int a_div, int c_perm, EpiArgs ep)
{
    constexpr int AP = 72, BP = DN + 8;
    constexpr int WN = DN / 4, NB = WN / 8;
    constexpr int A_LO = 64 * AP;
    constexpr int B_OFF = 2 * 64 * AP;
    constexpr int B_LO  = B_OFF + 64 * BP;
    constexpr int SBUF  = 2 * 64 * AP + 2 * 64 * BP;

    extern __shared__ bf16 sm[];
    const unsigned sbase = smem_u32(sm);

    const int tid = threadIdx.x, wid = tid >> 5, lane = tid & 31;
    const int mt = blockIdx.x;
    const int z  = blockIdx.z;
    const int a_idx = z / a_div;
    const int cz = c_perm ? ((z % a_div) * (gridDim.z / a_div) + a_idx) : z;
    const bf16* Bhi = Bhi_g + (size_t)z * NN * DN;
    const bf16* Blo = Blo_g + (size_t)z * NN * DN;
    const bf16* Ahi = g_Ahi + ((size_t)a_idx * NN + (size_t)mt * 64) * NN;
    const bf16* Alo = g_Alo + ((size_t)a_idx * NN + (size_t)mt * 64) * NN;

    const int wm = wid >> 2, wn = wid & 3;      // 2 x 4
    const int m0w = wm * 32, n0w = wn * WN;

    auto stage = [&](int ch, int buf) {
        const int k0 = ch * 64;
        const unsigned db = sbase + 2u * (unsigned)(buf * SBUF);
        #pragma unroll
        for (int it = 0; it < 2; it++) {
            int item = tid + it * 256, r = item >> 3, c = item & 7;
            cp16(db + 2u * (r * AP + c * 8),        Ahi + (size_t)r * NN + k0 + c * 8);
            cp16(db + 2u * (A_LO + r * AP + c * 8), Alo + (size_t)r * NN + k0 + c * 8);
        }
        #pragma unroll
        for (int it = 0; it < DN / 32; it++) {
            int item = tid + it * 256, r = item / (DN / 8), c = item % (DN / 8);
            cp16(db + 2u * (B_OFF + r * BP + c * 8), Bhi + (size_t)(k0 + r) * DN + c * 8);
            cp16(db + 2u * (B_LO  + r * BP + c * 8), Blo + (size_t)(k0 + r) * DN + c * 8);
        }
        cp_commit();
    };

    float acc[2][NB][4];
    #pragma unroll
    for (int i = 0; i < 2; i++)
        #pragma unroll
        for (int j = 0; j < NB; j++)
            #pragma unroll
            for (int q = 0; q < 4; q++) acc[i][j][q] = 0.f;

    stage(0, 0);
    for (int ch = 0; ch < 16; ch++) {
        const int buf = ch & 1;
        cp_wait<0>();                            // chunk ch staged
        __syncthreads();                         // visible; prev buffer idle
        if (ch < 15) stage(ch + 1, buf ^ 1);     // overlaps with compute below
        const unsigned aB = sbase + 2u * (unsigned)(buf * SBUF);
        #pragma unroll
        for (int ks = 0; ks < 4; ks++) {
            const int kk = ks * 16;
            unsigned ah[2][4], al[2][4];
            #pragma unroll
            for (int mi = 0; mi < 2; mi++) {
                unsigned row = m0w + mi * 16 + (lane & 15);
                unsigned col = kk + (lane >> 4) * 8;
                ldm_x4(ah[mi][0], ah[mi][1], ah[mi][2], ah[mi][3],
                       aB + 2u * (row * AP + col));
                ldm_x4(al[mi][0], al[mi][1], al[mi][2], al[mi][3],
                       aB + 2u * (A_LO + row * AP + col));
            }
            unsigned bh[NB][2], bl[NB][2];
            #pragma unroll
            for (int ni = 0; ni < NB; ni += 2) {
                unsigned row = kk + (lane & 15);
                unsigned col = n0w + ni * 8 + (lane >> 4) * 8;
                ldm_x4t(bh[ni][0], bh[ni][1], bh[ni+1][0], bh[ni+1][1],
                        aB + 2u * (B_OFF + row * BP + col));
                ldm_x4t(bl[ni][0], bl[ni][1], bl[ni+1][0], bl[ni+1][1],
                        aB + 2u * (B_LO + row * BP + col));
            }
            #pragma unroll
            for (int mi = 0; mi < 2; mi++)
                #pragma unroll
                for (int ni = 0; ni < NB; ni++) {
                    mma_bf16(acc[mi][ni], ah[mi], bh[ni]);
                    mma_bf16(acc[mi][ni], ah[mi], bl[ni]);
                    mma_bf16(acc[mi][ni], al[mi], bh[ni]);
                }
        }
    }

    const int g4 = lane >> 2, t4 = lane & 3;

    if (ep.emode == 0) {   // AX: bf16 hi/lo out
        bf16* ohi = g_AXhi + (size_t)cz * NN * DIN;
        bf16* olo = g_AXlo + (size_t)cz * NN * DIN;
        #pragma unroll
        for (int mi = 0; mi < 2; mi++)
            #pragma unroll
            for (int ni = 0; ni < NB; ni++) {
                int r0 = mt * 64 + m0w + mi * 16 + g4;
                int c  = n0w + ni * 8 + t4 * 2;
                store_hilo(ohi, olo, (size_t)r0 * DN + c, acc[mi][ni][0], acc[mi][ni][1]);
                store_hilo(ohi, olo, (size_t)(r0 + 8) * DN + c, acc[mi][ni][2], acc[mi][ni][3]);
            }
        return;
    }

    if constexpr (DN == 128) {
        __syncthreads();                        // all warps done with stage buffers
        const int gr0 = mt * 64;
        const int goff = (ep.emode >= 3) ? 64 : 0;
        const int Kd = goff ? 192 : 128;

        frag2act<4>(acc, sm, goff, m0w, n0w, lane);
        if (goff) {   // AX prefix, k-cols 0..63
            const bf16* axh = g_AXhi + ((size_t)(ep.t * BB + z) * NN + gr0) * DIN;
            const bf16* axl = g_AXlo + ((size_t)(ep.t * BB + z) * NN + gr0) * DIN;
            #pragma unroll
            for (int it = 0; it < 2; it++) {
                int item = tid + it * 256, r = item >> 3, c = (item & 7) * 8;
                *(uint4*)(sm + r * AP2 + c) = *(const uint4*)(axh + (size_t)r * DIN + c);
                *(uint4*)(sm + ACT_LO + r * AP2 + c) = *(const uint4*)(axl + (size_t)r * DIN + c);
            }
        }

        float e[2][4][4];
        const int n0e = wn * 32;
        epi_gemm<4>(sm, sbase, Kd, 136, g_Whi + ep.w1, g_Wlo + ep.w1, 128,
                    tid, lane, m0w, n0e, e);

        if (ep.emode == 1) {                 // U = tanh(.)
            #pragma unroll
            for (int mi = 0; mi < 2; mi++)
                #pragma unroll
                for (int ni = 0; ni < 4; ni++) {
                    int c = n0e + ni * 8 + t4 * 2;
                    float2 bv = *(const float2*)(ep.b1 + c);
                    size_t i0 = ((size_t)z * NN + gr0 + m0w + mi * 16 + g4) * DR + c;
                    size_t i1 = i0 + (size_t)8 * DR;
                    store_hilo(ep.ohi, ep.olo, i0, tanhf(e[mi][ni][0] + bv.x),
                                                 tanhf(e[mi][ni][1] + bv.y));
                    store_hilo(ep.ohi, ep.olo, i1, tanhf(e[mi][ni][2] + bv.x),
                                                 tanhf(e[mi][ni][3] + bv.y));
                }
        } else if (ep.emode == 2) {          // HV1 = H + v*DT (+ head)
            #pragma unroll
            for (int mi = 0; mi < 2; mi++)
                #pragma unroll
                for (int ni = 0; ni < 4; ni++) {
                    int c = n0e + ni * 8 + t4 * 2;
                    float2 bv = *(const float2*)(ep.b1 + c);
                    size_t i0 = ((size_t)z * NN + gr0 + m0w + mi * 16 + g4) * DR + c;
                    size_t i1 = i0 + (size_t)8 * DR;
                    float2 h0 = *(const float2*)(g_H + i0);
                    float2 h1 = *(const float2*)(g_H + i1);
                    float v0 = h0.x + (e[mi][ni][0] + bv.x) * DT_C;
                    float v1 = h0.y + (e[mi][ni][1] + bv.y) * DT_C;
                    float v2 = h1.x + (e[mi][ni][2] + bv.x) * DT_C;
                    float v3 = h1.y + (e[mi][ni][3] + bv.y) * DT_C;
                    *(float2*)(ep.of32 + i0) = make_float2(v0, v1);
                    *(float2*)(ep.of32 + i1) = make_float2(v2, v3);
                    store_hilo(ep.ohi, ep.olo, i0, v0, v1);
                    store_hilo(ep.ohi, ep.olo, i1, v2, v3);
                    e[mi][ni][0] = v0; e[mi][ni][1] = v1;
                    e[mi][ni][2] = v2; e[mi][ni][3] = v3;
                }
            if (ep.t >= 1) {                 // head: out = HV1 @ Wo + bo
                __syncthreads();
                frag2act<4>(e, sm, 0, m0w, n0e, lane);
                float e2[2][2][4];
                epi_gemm<2>(sm, sbase, 128, 72, g_Whi + ep.w2, g_Wlo + ep.w2, 64,
                            tid, lane, m0w, wn * 16, e2);
                #pragma unroll
                for (int mi = 0; mi < 2; mi++)
                    #pragma unroll
                    for (int ni = 0; ni < 2; ni++) {
                        int c = wn * 16 + ni * 8 + t4 * 2;
                        float2 bv = *(const float2*)(ep.b2 + c);
                        int r0 = gr0 + m0w + mi * 16 + g4;
                        size_t o0 = ((size_t)(z * (TT - 1) + ep.t - 1) * NN + r0) * DIN + c;
                        size_t o1 = o0 + (size_t)8 * DIN;
                        *(float2*)(ep.dout + o0) =
                            make_float2(e2[mi][ni][0] + bv.x, e2[mi][ni][1] + bv.y);
                        *(float2*)(ep.dout + o1) =
                            make_float2(e2[mi][ni][2] + bv.x, e2[mi][ni][3] + bv.y);
                    }
            }
        } else if (ep.emode == 3) {          // Z = sigm ; RH = sigm * HV1
            #pragma unroll
            for (int mi = 0; mi < 2; mi++)
                #pragma unroll
                for (int ni = 0; ni < 4; ni++) {
                    int c = n0e + ni * 8 + t4 * 2;
                    float2 bv = *(const float2*)(ep.b1 + c);
                    size_t i0 = ((size_t)z * NN + gr0 + m0w + mi * 16 + g4) * DR + c;
                    size_t i1 = i0 + (size_t)8 * DR;
                    *(float2*)(g_Z + i0) = make_float2(sigm(e[mi][ni][0] + bv.x),
                                                       sigm(e[mi][ni][1] + bv.y));
                    *(float2*)(g_Z + i1) = make_float2(sigm(e[mi][ni][2] + bv.x),
                                                       sigm(e[mi][ni][3] + bv.y));
                }
            float e2[2][4][4];
            epi_gemm<4>(sm, sbase, 192, 136, g_Whi + ep.w2, g_Wlo + ep.w2, 128,
                        tid, lane, m0w, n0e, e2);
            #pragma unroll
            for (int mi = 0; mi < 2; mi++)
                #pragma unroll
                for (int ni = 0; ni < 4; ni++) {
                    int c = n0e + ni * 8 + t4 * 2;
                    float2 bv = *(const float2*)(ep.b2 + c);
                    size_t i0 = ((size_t)z * NN + gr0 + m0w + mi * 16 + g4) * DR + c;
                    size_t i1 = i0 + (size_t)8 * DR;
                    float2 hv0 = *(const float2*)(g_HV1 + i0);
                    float2 hv1 = *(const float2*)(g_HV1 + i1);
                    store_hilo(ep.ohi, ep.olo, i0, sigm(e2[mi][ni][0] + bv.x) * hv0.x,
                                                 sigm(e2[mi][ni][1] + bv.y) * hv0.y);
                    store_hilo(ep.ohi, ep.olo, i1, sigm(e2[mi][ni][2] + bv.x) * hv1.x,
                                                 sigm(e2[mi][ni][3] + bv.y) * hv1.y);
                }
        } else {                             // emode 4: H = blend
            const float ob = g_OBS[ep.t * BB + z];
            #pragma unroll
            for (int mi = 0; mi < 2; mi++)
                #pragma unroll
                for (int ni = 0; ni < 4; ni++) {
                    int c = n0e + ni * 8 + t4 * 2;
                    float2 bv = *(const float2*)(ep.b1 + c);
                    size_t i0 = ((size_t)z * NN + gr0 + m0w + mi * 16 + g4) * DR + c;
                    size_t i1 = i0 + (size_t)8 * DR;
                    float2 zz0 = *(const float2*)(g_Z + i0);
                    float2 zz1 = *(const float2*)(g_Z + i1);
                    float2 h0 = *(const float2*)(g_HV1 + i0);
                    float2 h1 = *(const float2*)(g_HV1 + i1);
                    float c0 = tanhf(e[mi][ni][0] + bv.x);
                    float c1 = tanhf(e[mi][ni][1] + bv.y);
                    float c2 = tanhf(e[mi][ni][2] + bv.x);
                    float c3 = tanhf(e[mi][ni][3] + bv.y);
                    float o0 = h0.x + (zz0.x * (c0 - h0.x)) * ob;
                    float o1 = h0.y + (zz0.y * (c1 - h0.y)) * ob;
                    float o2 = h1.x + (zz1.x * (c2 - h1.x)) * ob;
                    float o3 = h1.y + (zz1.y * (c3 - h1.y)) * ob;
                    *(float2*)(ep.of32 + i0) = make_float2(o0, o1);
                    *(float2*)(ep.of32 + i1) = make_float2(o2, o3);
                    store_hilo(ep.ohi, ep.olo, i0, o0, o1);
                    store_hilo(ep.ohi, ep.olo, i1, o2, o3);
                }
        }
    }
}

// --------------------------- small utility kernels -------------------------
__global__ void __launch_bounds__(256) convA_kernel(const float* __restrict__ A)
{
    const size_t r = blockIdx.x;
    const float* src = A + r * NN;
    bf16* dhi = g_Ahi + r * NN;
    bf16* dlo = g_Alo + r * NN;
    int i = threadIdx.x * 4;
    float4 v = *(const float4*)(src + i);
    bf16 hx = __float2bfloat16(v.x), hy = __float2bfloat16(v.y);
    bf16 hz = __float2bfloat16(v.z), hw = __float2bfloat16(v.w);
    dhi[i+0] = hx; dhi[i+1] = hy; dhi[i+2] = hz; dhi[i+3] = hw;
    dlo[i+0] = __float2bfloat16(v.x - __bfloat162float(hx));
    dlo[i+1] = __float2bfloat16(v.y - __bfloat162float(hy));
    dlo[i+2] = __float2bfloat16(v.z - __bfloat162float(hz));
    dlo[i+3] = __float2bfloat16(v.w - __bfloat162float(hw));
}

// all 7 weights in one launch; blockIdx.y selects
__global__ void __launch_bounds__(256) convWall_kernel(
    const float* W0, const float* W1, const float* Wou, const float* Wz,
    const float* Wr, const float* Wh, const float* Wo)
{
    const float* W; long off; int n;
    switch (blockIdx.y) {
        case 0: W = W0;  off = OW0;   n = 16384; break;
        case 1: W = W1;  off = OW1;   n = 16384; break;
        case 2: W = Wou; off = OWOUT; n = 16384; break;
        case 3: W = Wz;  off = OWZ;   n = 24576; break;
        case 4: W = Wr;  off = OWR;   n = 24576; break;
        case 5: W = Wh;  off = OWH;   n = 24576; break;
        default: W = Wo; off = OWO;   n = 8192;  break;
    }
    int i = blockIdx.x * 256 + threadIdx.x;
    if (i >= n) return;
    float v = W[i];
    bf16 h = __float2bfloat16(v);
    g_Whi[off + i] = h;
    g_Wlo[off + i] = __float2bfloat16(v - __bfloat162float(h));
}

__global__ void __launch_bounds__(256) xmask_kernel(
    const float4* __restrict__ v, const float4* __restrict__ m)
{
    int i = blockIdx.x * 256 + threadIdx.x;
    float4 a = v[i], b = m[i];
    float x[4] = {a.x*b.x, a.y*b.y, a.z*b.z, a.w*b.w};
    bf16 hi[4], lo[4];
    #pragma unroll
    for (int j = 0; j < 4; j++) {
        hi[j] = __float2bfloat16(x[j]);
        lo[j] = __float2bfloat16(x[j] - __bfloat162float(hi[j]));
    }
    *(uint2*)&g_Xhi[(size_t)i*4] = *(uint2*)hi;
    *(uint2*)&g_Xlo[(size_t)i*4] = *(uint2*)lo;
}

__global__ void __launch_bounds__(256) inith_kernel(const float* __restrict__ h0)
{
    int i = blockIdx.x * 256 + threadIdx.x;
    float v = h0[i & (DR - 1)];
    g_H[i] = v;
    bf16 h = __float2bfloat16(v);
    g_Hhi[i] = h;
    g_Hlo[i] = __float2bfloat16(v - __bfloat162float(h));
}

__global__ void __launch_bounds__(256) obs_kernel(const float* __restrict__ masks)
{
    __shared__ float sh[256];
    int bt = blockIdx.x;
    const float* p = masks + (size_t)bt * (NN * DIN);
    float s = 0.f;
    for (int i = threadIdx.x; i < NN * DIN; i += 256) s += fabsf(p[i]);
    sh[threadIdx.x] = s; __syncthreads();
    for (int o = 128; o > 0; o >>= 1) {
        if (threadIdx.x < o) sh[threadIdx.x] += sh[threadIdx.x + o];
        __syncthreads();
    }
    if (threadIdx.x == 0) {
        int b = bt >> 5, t = bt & 31;
        g_OBS[t * BB + b] = (sh[0] > 1e-4f) ? 1.f : 0.f;
    }
}

// ------------------------------- launch ------------------------------------
extern "C" void kernel_launch(void* const* d_in, const int* in_sizes, int n_in,
                              void* d_out, int out_size)
{
    const float* values = (const float*)d_in[0];
    const float* masks  = (const float*)d_in[1];
    const float* A      = (const float*)d_in[2];
    const float* h0     = (const float*)d_in[3];
    const float* W0  = (const float*)d_in[4];  const float* b0v = (const float*)d_in[5];
    const float* W1  = (const float*)d_in[6];  const float* b1v = (const float*)d_in[7];
    const float* Wou = (const float*)d_in[8];  const float* bou = (const float*)d_in[9];
    const float* Wz  = (const float*)d_in[10]; const float* bz  = (const float*)d_in[11];
    const float* Wr  = (const float*)d_in[12]; const float* br  = (const float*)d_in[13];
    const float* Wh  = (const float*)d_in[14]; const float* bh  = (const float*)d_in[15];
    const float* Wo  = (const float*)d_in[16]; const float* bo  = (const float*)d_in[17];
    float* out = (float*)d_out;

    float *H, *HV1;
    bf16 *Xhi, *Xlo, *Hhi, *Hlo, *HV1hi, *HV1lo, *Uhi, *Ulo, *RHhi, *RHlo;
    cudaGetSymbolAddress((void**)&H,   g_H);
    cudaGetSymbolAddress((void**)&HV1, g_HV1);
    cudaGetSymbolAddress((void**)&Xhi, g_Xhi);   cudaGetSymbolAddress((void**)&Xlo, g_Xlo);
    cudaGetSymbolAddress((void**)&Hhi, g_Hhi);   cudaGetSymbolAddress((void**)&Hlo, g_Hlo);
    cudaGetSymbolAddress((void**)&HV1hi, g_HV1hi); cudaGetSymbolAddress((void**)&HV1lo, g_HV1lo);
    cudaGetSymbolAddress((void**)&Uhi, g_Uhi);   cudaGetSymbolAddress((void**)&Ulo, g_Ulo);
    cudaGetSymbolAddress((void**)&RHhi, g_RHhi); cudaGetSymbolAddress((void**)&RHlo, g_RHlo);

    // dyn smem: 2 stage buffers x (A 2*64*72 + B 2*64*(DN+8)) bf16
    const int SM128 = 2 * (2*64*72 + 2*64*136) * 2;   // 106496 B -> 2 CTAs/SM
    const int SM64  = 2 * (2*64*72 + 2*64*72)  * 2;   //  73728 B -> 2 CTAs/SM
    cudaFuncSetAttribute(agT_kernel<128>, cudaFuncAttributeMaxDynamicSharedMemorySize, SM128);
    cudaFuncSetAttribute(agT_kernel<64>,  cudaFuncAttributeMaxDynamicSharedMemorySize, SM64);

    EpiArgs ax{0, 0, 0, 0, nullptr, nullptr, nullptr, nullptr, nullptr, nullptr};

    // --- precompute (ordered so ncu -s 5 captures agT<64>) ---
    convA_kernel<<<BB*NN, 256>>>(A);                                  // 0
    convWall_kernel<<<dim3(96, 7), 256>>>(W0, W1, Wou, Wz, Wr, Wh, Wo); // 1
    xmask_kernel<<<(BB*TT*NN*DIN)/4/256, 256>>>(
        (const float4*)values, (const float4*)masks);                 // 2
    obs_kernel<<<BB*TT, 256>>>(masks);                                // 3
    inith_kernel<<<(BB*NN*DR)/256, 256>>>(h0);                        // 4
    agT_kernel<DIN><<<dim3(16, 1, BB*TT), 256, SM64>>>(Xhi, Xlo, TT, 1, ax); // 5

    auto AGE = [&](const bf16* bhi, const bf16* blo, EpiArgs ep) {
        agT_kernel<DR><<<dim3(16, 1, BB), 256, SM128>>>(bhi, blo, 1, 0, ep);
    };
    auto ODE = [&](const bf16* hhi, const bf16* hlo, float* tf, bf16* thi, bf16* tlo,
                   int t) {
        AGE(hhi, hlo, {1, t, OW0, 0, b0v, nullptr, nullptr, Uhi, Ulo, nullptr});
        AGE(Uhi, Ulo, {1, t, OW1, 0, b1v, nullptr, nullptr, Uhi, Ulo, nullptr});
        AGE(Uhi, Ulo, {2, t, OWOUT, OWO, bou, bo, tf, thi, tlo, out});
    };

    // iteration 0: h = h + ode(h)*DT (t=-1: no head)
    ODE(Hhi, Hlo, H, Hhi, Hlo, -1);

    for (int t = 0; t < TT; t++) {
        ODE(Hhi, Hlo, HV1, HV1hi, HV1lo, t);       // + output head for t>=1
        if (t < TT - 1) {
            AGE(HV1hi, HV1lo, {3, t, OWZ, OWR, bz, br, nullptr, RHhi, RHlo, nullptr});
            AGE(RHhi, RHlo,   {4, t, OWH, 0, bh, nullptr, H, Hhi, Hlo, nullptr});
        }
    }
}

// round 11
// speedup vs baseline: 1.0122x; 1.0122x over previous
#include <cuda_runtime.h>
#include <cuda_bf16.h>
#include <cstdint>
#include <math.h>

#define BB 8
#define TT 32
#define NN 1024
#define DIN 64
#define DR 128
#define DT_C 0.25f
typedef __nv_bfloat16 bf16;

// weight arena element offsets
#define OW0 0
#define OW1 16384
#define OWOUT 32768
#define OWZ 49152
#define OWR 73728
#define OWH 98304
#define OWO 122880

// ------------------------- device scratch (no allocs) ----------------------
__device__ bf16 g_Ahi[(size_t)BB*NN*NN];
__device__ bf16 g_Alo[(size_t)BB*NN*NN];
__device__ bf16 g_Xhi[(size_t)BB*TT*NN*DIN];
__device__ bf16 g_Xlo[(size_t)BB*TT*NN*DIN];
__device__ bf16 g_AXhi[(size_t)TT*BB*NN*DIN];
__device__ bf16 g_AXlo[(size_t)TT*BB*NN*DIN];
__device__ float g_H[BB*NN*DR];
__device__ bf16 g_Hhi[BB*NN*DR], g_Hlo[BB*NN*DR];
__device__ float g_HV1[BB*NN*DR];
__device__ bf16 g_HV1hi[BB*NN*DR], g_HV1lo[BB*NN*DR];
__device__ bf16 g_Uhi[BB*NN*DR], g_Ulo[BB*NN*DR];
__device__ bf16 g_RHhi[BB*NN*DR], g_RHlo[BB*NN*DR];
__device__ float g_Z[BB*NN*DR];
__device__ float g_OBS[TT*BB];
__device__ bf16 g_Whi[131072], g_Wlo[131072];

struct EpiArgs {
    int emode, t;            // 0 AX, 1 tanh->U, 2 hv1(+head), 3 Z&RH, 4 Hblend
    long w1, w2;
    const float *b1, *b2;
    float* of32;
    bf16 *ohi, *olo;
    float* dout;
};

// ----------------------------- PTX helpers ---------------------------------
__device__ __forceinline__ void pdl_trigger() {
    asm volatile("griddepcontrol.launch_dependents;" ::: "memory");
}
__device__ __forceinline__ void pdl_wait() {
    asm volatile("griddepcontrol.wait;" ::: "memory");
}
__device__ __forceinline__ unsigned smem_u32(const void* p) {
    unsigned a;
    asm("{ .reg .u64 t; cvta.to.shared.u64 t, %1; cvt.u32.u64 %0, t; }"
        : "=r"(a) : "l"(p));
    return a;
}
__device__ __forceinline__ void ldm_x4(unsigned& r0, unsigned& r1,
                                       unsigned& r2, unsigned& r3, unsigned a) {
    asm volatile("ldmatrix.sync.aligned.m8n8.x4.shared.b16 {%0,%1,%2,%3}, [%4];"
                 : "=r"(r0), "=r"(r1), "=r"(r2), "=r"(r3) : "r"(a));
}
__device__ __forceinline__ void ldm_x2t(unsigned& r0, unsigned& r1, unsigned a) {
    asm volatile("ldmatrix.sync.aligned.m8n8.x2.trans.shared.b16 {%0,%1}, [%2];"
                 : "=r"(r0), "=r"(r1) : "r"(a));
}
__device__ __forceinline__ void ldm_x4t(unsigned& r0, unsigned& r1,
                                        unsigned& r2, unsigned& r3, unsigned a) {
    asm volatile("ldmatrix.sync.aligned.m8n8.x4.trans.shared.b16 {%0,%1,%2,%3}, [%4];"
                 : "=r"(r0), "=r"(r1), "=r"(r2), "=r"(r3) : "r"(a));
}
__device__ __forceinline__ void mma_bf16(float* c, const unsigned* A, const unsigned* B) {
    asm volatile(
        "mma.sync.aligned.m16n8k16.row.col.f32.bf16.bf16.f32 "
        "{%0,%1,%2,%3}, {%4,%5,%6,%7}, {%8,%9}, {%0,%1,%2,%3};"
        : "+f"(c[0]), "+f"(c[1]), "+f"(c[2]), "+f"(c[3])
        : "r"(A[0]), "r"(A[1]), "r"(A[2]), "r"(A[3]), "r"(B[0]), "r"(B[1]));
}
__device__ __forceinline__ void cp16(unsigned s, const void* g) {
    asm volatile("cp.async.cg.shared.global [%0], [%1], 16;" :: "r"(s), "l"(g));
}
__device__ __forceinline__ void cp_commit() { asm volatile("cp.async.commit_group;"); }
template<int N> __device__ __forceinline__ void cp_wait() {
    asm volatile("cp.async.wait_group %0;" :: "n"(N));
}
__device__ __forceinline__ void store_hilo(bf16* hi, bf16* lo, size_t idx,
                                           float a, float b) {
    __nv_bfloat162 h = __floats2bfloat162_rn(a, b);
    *(unsigned*)(hi + idx) = *reinterpret_cast<unsigned*>(&h);
    __nv_bfloat162 l = __floats2bfloat162_rn(a - __bfloat162float(h.x),
                                             b - __bfloat162float(h.y));
    *(unsigned*)(lo + idx) = *reinterpret_cast<unsigned*>(&l);
}
__device__ __forceinline__ float sigm(float x) { return 1.f / (1.f + expf(-x)); }

// epilogue smem layout (elements)
#define AP2 200
#define ACT_LO 12800              // 64*AP2
#define WBOFF 25600               // 2*64*AP2

// epilogue GEMM: act tile (smem) x W chunk -> e[2][NBE][4]; 256 threads
template<int NBE>
__device__ __forceinline__ void epi_gemm(
    bf16* sm, unsigned sbase, int Kd, int WP,
    const bf16* Whi, const bf16* Wlo, int Dout,
    int tid, int lane, int m0w, int n0e, float (&e)[2][NBE][4])
{
    #pragma unroll
    for (int i = 0; i < 2; i++)
        #pragma unroll
        for (int j = 0; j < NBE; j++)
            #pragma unroll
            for (int q = 0; q < 4; q++) e[i][j][q] = 0.f;
    const int wlo = WBOFF + 64 * WP;
    for (int k0 = 0; k0 < Kd; k0 += 64) {
        __syncthreads();
        const int du4 = Dout / 8;
        for (int it = tid; it < 64 * du4; it += 256) {
            int r = it / du4, c = (it % du4) * 8;
            cp16(sbase + 2u * (WBOFF + r * WP + c),
                 Whi + (size_t)(k0 + r) * Dout + c);
            cp16(sbase + 2u * (wlo + r * WP + c),
                 Wlo + (size_t)(k0 + r) * Dout + c);
        }
        cp_commit();
        cp_wait<0>();
        __syncthreads();
        #pragma unroll
        for (int ks = 0; ks < 4; ks++) {
            const int kk = ks * 16;
            unsigned ah[2][4], al[2][4];
            #pragma unroll
            for (int mi = 0; mi < 2; mi++) {
                unsigned row = m0w + mi * 16 + (lane & 15);
                unsigned col = k0 + kk + (lane >> 4) * 8;
                ldm_x4(ah[mi][0], ah[mi][1], ah[mi][2], ah[mi][3],
                       sbase + 2u * (row * AP2 + col));
                ldm_x4(al[mi][0], al[mi][1], al[mi][2], al[mi][3],
                       sbase + 2u * (ACT_LO + row * AP2 + col));
            }
            unsigned bh[NBE][2], bl[NBE][2];
            if constexpr (NBE >= 2) {
                #pragma unroll
                for (int ni = 0; ni < NBE; ni += 2) {
                    unsigned row = kk + (lane & 15);
                    unsigned col = n0e + ni * 8 + (lane >> 4) * 8;
                    ldm_x4t(bh[ni][0], bh[ni][1], bh[ni+1][0], bh[ni+1][1],
                            sbase + 2u * (WBOFF + row * WP + col));
                    ldm_x4t(bl[ni][0], bl[ni][1], bl[ni+1][0], bl[ni+1][1],
                            sbase + 2u * (wlo + row * WP + col));
                }
            } else {
                unsigned row = kk + (lane & 15);
                ldm_x2t(bh[0][0], bh[0][1], sbase + 2u * (WBOFF + row * WP + n0e));
                ldm_x2t(bl[0][0], bl[0][1], sbase + 2u * (wlo + row * WP + n0e));
            }
            #pragma unroll
            for (int mi = 0; mi < 2; mi++)
                #pragma unroll
                for (int ni = 0; ni < NBE; ni++) {
                    mma_bf16(e[mi][ni], ah[mi], bh[ni]);
                    mma_bf16(e[mi][ni], ah[mi], bl[ni]);
                    mma_bf16(e[mi][ni], al[mi], bh[ni]);
                }
        }
    }
}

template<int NBX>
__device__ __forceinline__ void frag2act(const float (&a)[2][NBX][4], bf16* sm,
                                         int goff, int m0, int n0, int lane)
{
    const int g4 = lane >> 2, t4 = lane & 3;
    #pragma unroll
    for (int mi = 0; mi < 2; mi++)
        #pragma unroll
        for (int ni = 0; ni < NBX; ni++) {
            int r0 = m0 + mi * 16 + g4;
            int c  = goff + n0 + ni * 8 + t4 * 2;
            store_hilo(sm, sm + ACT_LO, (size_t)r0 * AP2 + c,
                       a[mi][ni][0], a[mi][ni][1]);
            store_hilo(sm, sm + ACT_LO, (size_t)(r0 + 8) * AP2 + c,
                       a[mi][ni][2], a[mi][ni][3]);
        }
}

// ---------------------------------------------------------------------------
// agT: C = A[z] @ B[z] (M=K=1024, N=DN) + fused epilogue (DN=128).
// 256 threads (8 warps: 2m x 4n), 3-stage cp.async, 1 barrier per chunk,
// register-pipelined fragments, PDL: trigger at entry, A-prefetch before
// griddepcontrol.wait, B staged after.
// ---------------------------------------------------------------------------
template<int DN>
__global__ void __launch_bounds__(256) agT_kernel(
    const bf16* __restrict__ Bhi_g, const bf16* __restrict__ Blo_g,
    int a_div, int c_perm, EpiArgs ep)
{
    constexpr int AP = 72, BP = DN + 8;
    constexpr int WN = DN / 4, NB = WN / 8;
    constexpr int A_LO = 64 * AP;
    constexpr int B_OFF = 2 * 64 * AP;
    constexpr int B_LO  = B_OFF + 64 * BP;
    constexpr int SBUF  = 2 * 64 * AP + 2 * 64 * BP;

    pdl_trigger();     // let the next launch in the chain roll out now

    extern __shared__ bf16 sm[];
    const unsigned sbase = smem_u32(sm);

    const int tid = threadIdx.x, wid = tid >> 5, lane = tid & 31;
    const int mt = blockIdx.x;
    const int z  = blockIdx.z;
    const int a_idx = z / a_div;
    const int cz = c_perm ? ((z % a_div) * (gridDim.z / a_div) + a_idx) : z;
    const bf16* Bhi = Bhi_g + (size_t)z * NN * DN;
    const bf16* Blo = Blo_g + (size_t)z * NN * DN;
    const bf16* Ahi = g_Ahi + ((size_t)a_idx * NN + (size_t)mt * 64) * NN;
    const bf16* Alo = g_Alo + ((size_t)a_idx * NN + (size_t)mt * 64) * NN;

    const int wm = wid >> 2, wn = wid & 3;      // 2 x 4
    const int m0w = wm * 32, n0w = wn * WN;

    auto stageA = [&](int ch, int buf) {        // dependency-free (g_Ahi const)
        const int k0 = ch * 64;
        const unsigned db = sbase + 2u * (unsigned)(buf * SBUF);
        #pragma unroll
        for (int it = 0; it < 2; it++) {
            int item = tid + it * 256, r = item >> 3, c = item & 7;
            cp16(db + 2u * (r * AP + c * 8),        Ahi + (size_t)r * NN + k0 + c * 8);
            cp16(db + 2u * (A_LO + r * AP + c * 8), Alo + (size_t)r * NN + k0 + c * 8);
        }
    };
    auto stageB = [&](int ch, int buf) {
        const int k0 = ch * 64;
        const unsigned db = sbase + 2u * (unsigned)(buf * SBUF);
        #pragma unroll
        for (int it = 0; it < DN / 32; it++) {
            int item = tid + it * 256, r = item / (DN / 8), c = item % (DN / 8);
            cp16(db + 2u * (B_OFF + r * BP + c * 8), Bhi + (size_t)(k0 + r) * DN + c * 8);
            cp16(db + 2u * (B_LO  + r * BP + c * 8), Blo + (size_t)(k0 + r) * DN + c * 8);
        }
    };
    auto stage = [&](int ch, int buf) { stageA(ch, buf); stageB(ch, buf); cp_commit(); };

    float acc[2][NB][4];
    #pragma unroll
    for (int i = 0; i < 2; i++)
        #pragma unroll
        for (int j = 0; j < NB; j++)
            #pragma unroll
            for (int q = 0; q < 4; q++) acc[i][j][q] = 0.f;

    // register-double-buffered fragments
    unsigned ah[2][2][4], al[2][2][4], bh[2][NB][2], bl[2][NB][2];
    auto ldfrag = [&](int ks, int pb, unsigned aB) {
        const int kk = ks * 16;
        #pragma unroll
        for (int mi = 0; mi < 2; mi++) {
            unsigned row = m0w + mi * 16 + (lane & 15);
            unsigned col = kk + (lane >> 4) * 8;
            ldm_x4(ah[pb][mi][0], ah[pb][mi][1], ah[pb][mi][2], ah[pb][mi][3],
                   aB + 2u * (row * AP + col));
            ldm_x4(al[pb][mi][0], al[pb][mi][1], al[pb][mi][2], al[pb][mi][3],
                   aB + 2u * (A_LO + row * AP + col));
        }
        #pragma unroll
        for (int ni = 0; ni < NB; ni += 2) {
            unsigned row = kk + (lane & 15);
            unsigned col = n0w + ni * 8 + (lane >> 4) * 8;
            ldm_x4t(bh[pb][ni][0], bh[pb][ni][1], bh[pb][ni+1][0], bh[pb][ni+1][1],
                    aB + 2u * (B_OFF + row * BP + col));
            ldm_x4t(bl[pb][ni][0], bl[pb][ni][1], bl[pb][ni+1][0], bl[pb][ni+1][1],
                    aB + 2u * (B_LO + row * BP + col));
        }
    };

    // prologue: prefetch A of chunks 0/1 while upstream kernel still runs
    stageA(0, 0);
    stageA(1, 1);
    pdl_wait();                    // upstream complete; B operand now valid
    stageB(0, 0); cp_commit();     // group0: A0 + A1 + B0
    stageB(1, 1); cp_commit();     // group1: B1

    for (int ch = 0; ch < 16; ch++) {
        const int buf = ch % 3;
        if (ch < 15) cp_wait<1>(); else cp_wait<0>();
        __syncthreads();                         // chunk ch visible; buf (ch+2)%3 idle
        if (ch <= 13) stage(ch + 2, (ch + 2) % 3);
        const unsigned aB = sbase + 2u * (unsigned)(buf * SBUF);
        ldfrag(0, 0, aB);
        #pragma unroll
        for (int ks = 0; ks < 4; ks++) {
            const int cur = ks & 1;
            if (ks < 3) ldfrag(ks + 1, cur ^ 1, aB);
            #pragma unroll
            for (int mi = 0; mi < 2; mi++)
                #pragma unroll
                for (int ni = 0; ni < NB; ni++) {
                    mma_bf16(acc[mi][ni], ah[cur][mi], bh[cur][ni]);
                    mma_bf16(acc[mi][ni], ah[cur][mi], bl[cur][ni]);
                    mma_bf16(acc[mi][ni], al[cur][mi], bh[cur][ni]);
                }
        }
    }

    const int g4 = lane >> 2, t4 = lane & 3;

    if (ep.emode == 0) {   // AX: bf16 hi/lo out
        bf16* ohi = g_AXhi + (size_t)cz * NN * DIN;
        bf16* olo = g_AXlo + (size_t)cz * NN * DIN;
        #pragma unroll
        for (int mi = 0; mi < 2; mi++)
            #pragma unroll
            for (int ni = 0; ni < NB; ni++) {
                int r0 = mt * 64 + m0w + mi * 16 + g4;
                int c  = n0w + ni * 8 + t4 * 2;
                store_hilo(ohi, olo, (size_t)r0 * DN + c, acc[mi][ni][0], acc[mi][ni][1]);
                store_hilo(ohi, olo, (size_t)(r0 + 8) * DN + c, acc[mi][ni][2], acc[mi][ni][3]);
            }
        return;
    }

    if constexpr (DN == 128) {
        __syncthreads();                        // stage buffers dead
        const int gr0 = mt * 64;
        const int goff = (ep.emode >= 3) ? 64 : 0;
        const int Kd = goff ? 192 : 128;

        frag2act<4>(acc, sm, goff, m0w, n0w, lane);
        if (goff) {   // AX prefix, k-cols 0..63
            const bf16* axh = g_AXhi + ((size_t)(ep.t * BB + z) * NN + gr0) * DIN;
            const bf16* axl = g_AXlo + ((size_t)(ep.t * BB + z) * NN + gr0) * DIN;
            #pragma unroll
            for (int it = 0; it < 2; it++) {
                int item = tid + it * 256, r = item >> 3, c = (item & 7) * 8;
                *(uint4*)(sm + r * AP2 + c) = *(const uint4*)(axh + (size_t)r * DIN + c);
                *(uint4*)(sm + ACT_LO + r * AP2 + c) = *(const uint4*)(axl + (size_t)r * DIN + c);
            }
        }

        float e[2][4][4];
        const int n0e = wn * 32;
        epi_gemm<4>(sm, sbase, Kd, 136, g_Whi + ep.w1, g_Wlo + ep.w1, 128,
                    tid, lane, m0w, n0e, e);

        if (ep.emode == 1) {                 // U = tanh(.)
            #pragma unroll
            for (int mi = 0; mi < 2; mi++)
                #pragma unroll
                for (int ni = 0; ni < 4; ni++) {
                    int c = n0e + ni * 8 + t4 * 2;
                    float2 bv = *(const float2*)(ep.b1 + c);
                    size_t i0 = ((size_t)z * NN + gr0 + m0w + mi * 16 + g4) * DR + c;
                    size_t i1 = i0 + (size_t)8 * DR;
                    store_hilo(ep.ohi, ep.olo, i0, tanhf(e[mi][ni][0] + bv.x),
                                                 tanhf(e[mi][ni][1] + bv.y));
                    store_hilo(ep.ohi, ep.olo, i1, tanhf(e[mi][ni][2] + bv.x),
                                                 tanhf(e[mi][ni][3] + bv.y));
                }
        } else if (ep.emode == 2) {          // HV1 = H + v*DT (+ head)
            #pragma unroll
            for (int mi = 0; mi < 2; mi++)
                #pragma unroll
                for (int ni = 0; ni < 4; ni++) {
                    int c = n0e + ni * 8 + t4 * 2;
                    float2 bv = *(const float2*)(ep.b1 + c);
                    size_t i0 = ((size_t)z * NN + gr0 + m0w + mi * 16 + g4) * DR + c;
                    size_t i1 = i0 + (size_t)8 * DR;
                    float2 h0 = *(const float2*)(g_H + i0);
                    float2 h1 = *(const float2*)(g_H + i1);
                    float v0 = h0.x + (e[mi][ni][0] + bv.x) * DT_C;
                    float v1 = h0.y + (e[mi][ni][1] + bv.y) * DT_C;
                    float v2 = h1.x + (e[mi][ni][2] + bv.x) * DT_C;
                    float v3 = h1.y + (e[mi][ni][3] + bv.y) * DT_C;
                    *(float2*)(ep.of32 + i0) = make_float2(v0, v1);
                    *(float2*)(ep.of32 + i1) = make_float2(v2, v3);
                    store_hilo(ep.ohi, ep.olo, i0, v0, v1);
                    store_hilo(ep.ohi, ep.olo, i1, v2, v3);
                    e[mi][ni][0] = v0; e[mi][ni][1] = v1;
                    e[mi][ni][2] = v2; e[mi][ni][3] = v3;
                }
            if (ep.t >= 1) {                 // head: out = HV1 @ Wo + bo
                __syncthreads();
                frag2act<4>(e, sm, 0, m0w, n0e, lane);
                float e2[2][2][4];
                epi_gemm<2>(sm, sbase, 128, 72, g_Whi + ep.w2, g_Wlo + ep.w2, 64,
                            tid, lane, m0w, wn * 16, e2);
                #pragma unroll
                for (int mi = 0; mi < 2; mi++)
                    #pragma unroll
                    for (int ni = 0; ni < 2; ni++) {
                        int c = wn * 16 + ni * 8 + t4 * 2;
                        float2 bv = *(const float2*)(ep.b2 + c);
                        int r0 = gr0 + m0w + mi * 16 + g4;
                        size_t o0 = ((size_t)(z * (TT - 1) + ep.t - 1) * NN + r0) * DIN + c;
                        size_t o1 = o0 + (size_t)8 * DIN;
                        *(float2*)(ep.dout + o0) =
                            make_float2(e2[mi][ni][0] + bv.x, e2[mi][ni][1] + bv.y);
                        *(float2*)(ep.dout + o1) =
                            make_float2(e2[mi][ni][2] + bv.x, e2[mi][ni][3] + bv.y);
                    }
            }
        } else if (ep.emode == 3) {          // Z = sigm ; RH = sigm * HV1
            #pragma unroll
            for (int mi = 0; mi < 2; mi++)
                #pragma unroll
                for (int ni = 0; ni < 4; ni++) {
                    int c = n0e + ni * 8 + t4 * 2;
                    float2 bv = *(const float2*)(ep.b1 + c);
                    size_t i0 = ((size_t)z * NN + gr0 + m0w + mi * 16 + g4) * DR + c;
                    size_t i1 = i0 + (size_t)8 * DR;
                    *(float2*)(g_Z + i0) = make_float2(sigm(e[mi][ni][0] + bv.x),
                                                       sigm(e[mi][ni][1] + bv.y));
                    *(float2*)(g_Z + i1) = make_float2(sigm(e[mi][ni][2] + bv.x),
                                                       sigm(e[mi][ni][3] + bv.y));
                }
            float e2[2][4][4];
            epi_gemm<4>(sm, sbase, 192, 136, g_Whi + ep.w2, g_Wlo + ep.w2, 128,
                        tid, lane, m0w, n0e, e2);
            #pragma unroll
            for (int mi = 0; mi < 2; mi++)
                #pragma unroll
                for (int ni = 0; ni < 4; ni++) {
                    int c = n0e + ni * 8 + t4 * 2;
                    float2 bv = *(const float2*)(ep.b2 + c);
                    size_t i0 = ((size_t)z * NN + gr0 + m0w + mi * 16 + g4) * DR + c;
                    size_t i1 = i0 + (size_t)8 * DR;
                    float2 hv0 = *(const float2*)(g_HV1 + i0);
                    float2 hv1 = *(const float2*)(g_HV1 + i1);
                    store_hilo(ep.ohi, ep.olo, i0, sigm(e2[mi][ni][0] + bv.x) * hv0.x,
                                                 sigm(e2[mi][ni][1] + bv.y) * hv0.y);
                    store_hilo(ep.ohi, ep.olo, i1, sigm(e2[mi][ni][2] + bv.x) * hv1.x,
                                                 sigm(e2[mi][ni][3] + bv.y) * hv1.y);
                }
        } else {                             // emode 4: H = blend
            const float ob = g_OBS[ep.t * BB + z];
            #pragma unroll
            for (int mi = 0; mi < 2; mi++)
                #pragma unroll
                for (int ni = 0; ni < 4; ni++) {
                    int c = n0e + ni * 8 + t4 * 2;
                    float2 bv = *(const float2*)(ep.b1 + c);
                    size_t i0 = ((size_t)z * NN + gr0 + m0w + mi * 16 + g4) * DR + c;
                    size_t i1 = i0 + (size_t)8 * DR;
                    float2 zz0 = *(const float2*)(g_Z + i0);
                    float2 zz1 = *(const float2*)(g_Z + i1);
                    float2 h0 = *(const float2*)(g_HV1 + i0);
                    float2 h1 = *(const float2*)(g_HV1 + i1);
                    float c0 = tanhf(e[mi][ni][0] + bv.x);
                    float c1 = tanhf(e[mi][ni][1] + bv.y);
                    float c2 = tanhf(e[mi][ni][2] + bv.x);
                    float c3 = tanhf(e[mi][ni][3] + bv.y);
                    float o0 = h0.x + (zz0.x * (c0 - h0.x)) * ob;
                    float o1 = h0.y + (zz0.y * (c1 - h0.y)) * ob;
                    float o2 = h1.x + (zz1.x * (c2 - h1.x)) * ob;
                    float o3 = h1.y + (zz1.y * (c3 - h1.y)) * ob;
                    *(float2*)(ep.of32 + i0) = make_float2(o0, o1);
                    *(float2*)(ep.of32 + i1) = make_float2(o2, o3);
                    store_hilo(ep.ohi, ep.olo, i0, o0, o1);
                    store_hilo(ep.ohi, ep.olo, i1, o2, o3);
                }
        }
    }
}

// --------------------------- small utility kernels -------------------------
__global__ void __launch_bounds__(256) convA_kernel(const float* __restrict__ A)
{
    const size_t r = blockIdx.x;
    const float* src = A + r * NN;
    bf16* dhi = g_Ahi + r * NN;
    bf16* dlo = g_Alo + r * NN;
    int i = threadIdx.x * 4;
    float4 v = *(const float4*)(src + i);
    bf16 hx = __float2bfloat16(v.x), hy = __float2bfloat16(v.y);
    bf16 hz = __float2bfloat16(v.z), hw = __float2bfloat16(v.w);
    dhi[i+0] = hx; dhi[i+1] = hy; dhi[i+2] = hz; dhi[i+3] = hw;
    dlo[i+0] = __float2bfloat16(v.x - __bfloat162float(hx));
    dlo[i+1] = __float2bfloat16(v.y - __bfloat162float(hy));
    dlo[i+2] = __float2bfloat16(v.z - __bfloat162float(hz));
    dlo[i+3] = __float2bfloat16(v.w - __bfloat162float(hw));
}

__global__ void __launch_bounds__(256) convWall_kernel(
    const float* W0, const float* W1, const float* Wou, const float* Wz,
    const float* Wr, const float* Wh, const float* Wo)
{
    const float* W; long off; int n;
    switch (blockIdx.y) {
        case 0: W = W0;  off = OW0;   n = 16384; break;
        case 1: W = W1;  off = OW1;   n = 16384; break;
        case 2: W = Wou; off = OWOUT; n = 16384; break;
        case 3: W = Wz;  off = OWZ;   n = 24576; break;
        case 4: W = Wr;  off = OWR;   n = 24576; break;
        case 5: W = Wh;  off = OWH;   n = 24576; break;
        default: W = Wo; off = OWO;   n = 8192;  break;
    }
    int i = blockIdx.x * 256 + threadIdx.x;
    if (i >= n) return;
    float v = W[i];
    bf16 h = __float2bfloat16(v);
    g_Whi[off + i] = h;
    g_Wlo[off + i] = __float2bfloat16(v - __bfloat162float(h));
}

__global__ void __launch_bounds__(256) xmask_kernel(
    const float4* __restrict__ v, const float4* __restrict__ m)
{
    int i = blockIdx.x * 256 + threadIdx.x;
    float4 a = v[i], b = m[i];
    float x[4] = {a.x*b.x, a.y*b.y, a.z*b.z, a.w*b.w};
    bf16 hi[4], lo[4];
    #pragma unroll
    for (int j = 0; j < 4; j++) {
        hi[j] = __float2bfloat16(x[j]);
        lo[j] = __float2bfloat16(x[j] - __bfloat162float(hi[j]));
    }
    *(uint2*)&g_Xhi[(size_t)i*4] = *(uint2*)hi;
    *(uint2*)&g_Xlo[(size_t)i*4] = *(uint2*)lo;
}

__global__ void __launch_bounds__(256) inith_kernel(const float* __restrict__ h0)
{
    int i = blockIdx.x * 256 + threadIdx.x;
    float v = h0[i & (DR - 1)];
    g_H[i] = v;
    bf16 h = __float2bfloat16(v);
    g_Hhi[i] = h;
    g_Hlo[i] = __float2bfloat16(v - __bfloat162float(h));
}

__global__ void __launch_bounds__(256) obs_kernel(const float* __restrict__ masks)
{
    __shared__ float sh[256];
    int bt = blockIdx.x;
    const float* p = masks + (size_t)bt * (NN * DIN);
    float s = 0.f;
    for (int i = threadIdx.x; i < NN * DIN; i += 256) s += fabsf(p[i]);
    sh[threadIdx.x] = s; __syncthreads();
    for (int o = 128; o > 0; o >>= 1) {
        if (threadIdx.x < o) sh[threadIdx.x] += sh[threadIdx.x + o];
        __syncthreads();
    }
    if (threadIdx.x == 0) {
        int b = bt >> 5, t = bt & 31;
        g_OBS[t * BB + b] = (sh[0] > 1e-4f) ? 1.f : 0.f;
    }
}

// ------------------------------- launch ------------------------------------
extern "C" void kernel_launch(void* const* d_in, const int* in_sizes, int n_in,
                              void* d_out, int out_size)
{
    const float* values = (const float*)d_in[0];
    const float* masks  = (const float*)d_in[1];
    const float* A      = (const float*)d_in[2];
    const float* h0     = (const float*)d_in[3];
    const float* W0  = (const float*)d_in[4];  const float* b0v = (const float*)d_in[5];
    const float* W1  = (const float*)d_in[6];  const float* b1v = (const float*)d_in[7];
    const float* Wou = (const float*)d_in[8];  const float* bou = (const float*)d_in[9];
    const float* Wz  = (const float*)d_in[10]; const float* bz  = (const float*)d_in[11];
    const float* Wr  = (const float*)d_in[12]; const float* br  = (const float*)d_in[13];
    const float* Wh  = (const float*)d_in[14]; const float* bh  = (const float*)d_in[15];
    const float* Wo  = (const float*)d_in[16]; const float* bo  = (const float*)d_in[17];
    float* out = (float*)d_out;

    float *H, *HV1;
    bf16 *Xhi, *Xlo, *Hhi, *Hlo, *HV1hi, *HV1lo, *Uhi, *Ulo, *RHhi, *RHlo;
    cudaGetSymbolAddress((void**)&H,   g_H);
    cudaGetSymbolAddress((void**)&HV1, g_HV1);
    cudaGetSymbolAddress((void**)&Xhi, g_Xhi);   cudaGetSymbolAddress((void**)&Xlo, g_Xlo);
    cudaGetSymbolAddress((void**)&Hhi, g_Hhi);   cudaGetSymbolAddress((void**)&Hlo, g_Hlo);
    cudaGetSymbolAddress((void**)&HV1hi, g_HV1hi); cudaGetSymbolAddress((void**)&HV1lo, g_HV1lo);
    cudaGetSymbolAddress((void**)&Uhi, g_Uhi);   cudaGetSymbolAddress((void**)&Ulo, g_Ulo);
    cudaGetSymbolAddress((void**)&RHhi, g_RHhi); cudaGetSymbolAddress((void**)&RHlo, g_RHlo);

    // dyn smem: 3 stage buffers x (A 2*64*72 + B 2*64*(DN+8)) bf16
    const int SM128 = 3 * (2*64*72 + 2*64*136) * 2;   // 159744 B
    const int SM64  = 3 * (2*64*72 + 2*64*72)  * 2;   // 110592 B
    cudaFuncSetAttribute(agT_kernel<128>, cudaFuncAttributeMaxDynamicSharedMemorySize, SM128);
    cudaFuncSetAttribute(agT_kernel<64>,  cudaFuncAttributeMaxDynamicSharedMemorySize, SM64);

    EpiArgs ax{0, 0, 0, 0, nullptr, nullptr, nullptr, nullptr, nullptr, nullptr};

    // --- precompute ---
    convA_kernel<<<BB*NN, 256>>>(A);
    convWall_kernel<<<dim3(96, 7), 256>>>(W0, W1, Wou, Wz, Wr, Wh, Wo);
    xmask_kernel<<<(BB*TT*NN*DIN)/4/256, 256>>>(
        (const float4*)values, (const float4*)masks);
    obs_kernel<<<BB*TT, 256>>>(masks);
    inith_kernel<<<(BB*NN*DR)/256, 256>>>(h0);

    // PDL launch config helpers
    cudaLaunchAttribute pdlAttr[1];
    pdlAttr[0].id = cudaLaunchAttributeProgrammaticStreamSerialization;
    pdlAttr[0].val.programmaticStreamSerializationAllowed = 1;

    {
        cudaLaunchConfig_t cfg = {};
        cfg.gridDim = dim3(16, 1, BB*TT);
        cfg.blockDim = dim3(256, 1, 1);
        cfg.dynamicSmemBytes = SM64;
        cfg.stream = 0;
        cfg.attrs = pdlAttr;
        cfg.numAttrs = 1;
        cudaLaunchKernelEx(&cfg, agT_kernel<DIN>, Xhi, Xlo, TT, 1, ax);
    }

    auto AGE = [&](const bf16* bhi, const bf16* blo, EpiArgs ep) {
        cudaLaunchConfig_t cfg = {};
        cfg.gridDim = dim3(16, 1, BB);
        cfg.blockDim = dim3(256, 1, 1);
        cfg.dynamicSmemBytes = SM128;
        cfg.stream = 0;
        cfg.attrs = pdlAttr;
        cfg.numAttrs = 1;
        cudaLaunchKernelEx(&cfg, agT_kernel<DR>, bhi, blo, 1, 0, ep);
    };
    auto ODE = [&](const bf16* hhi, const bf16* hlo, float* tf, bf16* thi, bf16* tlo,
                   int t) {
        AGE(hhi, hlo, {1, t, OW0, 0, b0v, nullptr, nullptr, Uhi, Ulo, nullptr});
        AGE(Uhi, Ulo, {1, t, OW1, 0, b1v, nullptr, nullptr, Uhi, Ulo, nullptr});
        AGE(Uhi, Ulo, {2, t, OWOUT, OWO, bou, bo, tf, thi, tlo, out});
    };

    // iteration 0: h = h + ode(h)*DT (t=-1: no head)
    ODE(Hhi, Hlo, H, Hhi, Hlo, -1);

    for (int t = 0; t < TT; t++) {
        ODE(Hhi, Hlo, HV1, HV1hi, HV1lo, t);       // + output head for t>=1
        if (t < TT - 1) {
            AGE(HV1hi, HV1lo, {3, t, OWZ, OWR, bz, br, nullptr, RHhi, RHlo, nullptr});
            AGE(RHhi, RHlo,   {4, t, OWH, 0, bh, nullptr, H, Hhi, Hlo, nullptr});
        }
    }
}

// round 13
// speedup vs baseline: 1.1302x; 1.1166x over previous
#include <cuda_runtime.h>
#include <cuda_bf16.h>
#include <cstdint>
#include <math.h>

#define BB 8
#define TT 32
#define NN 1024
#define DIN 64
#define DR 128
#define DT_C 0.25f
typedef __nv_bfloat16 bf16;

// weight arena element offsets
#define OW0 0
#define OW1 16384
#define OWOUT 32768
#define OWZ 49152
#define OWR 73728
#define OWH 98304
#define OWO 122880

// ------------------------- device scratch (no allocs) ----------------------
__device__ bf16 g_Ahi[(size_t)BB*NN*NN];
__device__ bf16 g_Alo[(size_t)BB*NN*NN];
__device__ bf16 g_Xhi[(size_t)BB*TT*NN*DIN];
__device__ bf16 g_Xlo[(size_t)BB*TT*NN*DIN];
__device__ bf16 g_AXhi[(size_t)TT*BB*NN*DIN];
__device__ bf16 g_AXlo[(size_t)TT*BB*NN*DIN];
__device__ float g_H[BB*NN*DR];
__device__ bf16 g_Hhi[BB*NN*DR], g_Hlo[BB*NN*DR];
__device__ float g_HV1[BB*NN*DR];
__device__ float g_G1[BB*NN*DR];
__device__ bf16 g_Uhi[BB*NN*DR], g_Ulo[BB*NN*DR];
__device__ bf16 g_RHhi[BB*NN*DR], g_RHlo[BB*NN*DR];
__device__ float g_Z[BB*NN*DR];
__device__ float g_OBS[TT*BB];
__device__ bf16 g_Whi[131072], g_Wlo[131072];

struct EpiArgs {
    int emode, t;        // 0 AX, 1 tanh(+G1 store), 2 hv1+gates+head, 4 Hblend
    long w1, w2, w3, w4;
    const float *b1, *b2, *b3, *b4;
    float *of32, *g1, *zout, *dout;
    bf16 *ohi, *olo, *rhhi, *rhlo;
};

// ----------------------------- PTX helpers ---------------------------------
__device__ __forceinline__ void pdl_trigger() {
    asm volatile("griddepcontrol.launch_dependents;" ::: "memory");
}
__device__ __forceinline__ void pdl_wait() {
    asm volatile("griddepcontrol.wait;" ::: "memory");
}
__device__ __forceinline__ unsigned smem_u32(const void* p) {
    unsigned a;
    asm("{ .reg .u64 t; cvta.to.shared.u64 t, %1; cvt.u32.u64 %0, t; }"
        : "=r"(a) : "l"(p));
    return a;
}
__device__ __forceinline__ void ldm_x4(unsigned& r0, unsigned& r1,
                                       unsigned& r2, unsigned& r3, unsigned a) {
    asm volatile("ldmatrix.sync.aligned.m8n8.x4.shared.b16 {%0,%1,%2,%3}, [%4];"
                 : "=r"(r0), "=r"(r1), "=r"(r2), "=r"(r3) : "r"(a));
}
__device__ __forceinline__ void ldm_x2t(unsigned& r0, unsigned& r1, unsigned a) {
    asm volatile("ldmatrix.sync.aligned.m8n8.x2.trans.shared.b16 {%0,%1}, [%2];"
                 : "=r"(r0), "=r"(r1) : "r"(a));
}
__device__ __forceinline__ void ldm_x4t(unsigned& r0, unsigned& r1,
                                        unsigned& r2, unsigned& r3, unsigned a) {
    asm volatile("ldmatrix.sync.aligned.m8n8.x4.trans.shared.b16 {%0,%1,%2,%3}, [%4];"
                 : "=r"(r0), "=r"(r1), "=r"(r2), "=r"(r3) : "r"(a));
}
__device__ __forceinline__ void mma_bf16(float* c, const unsigned* A, const unsigned* B) {
    asm volatile(
        "mma.sync.aligned.m16n8k16.row.col.f32.bf16.bf16.f32 "
        "{%0,%1,%2,%3}, {%4,%5,%6,%7}, {%8,%9}, {%0,%1,%2,%3};"
        : "+f"(c[0]), "+f"(c[1]), "+f"(c[2]), "+f"(c[3])
        : "r"(A[0]), "r"(A[1]), "r"(A[2]), "r"(A[3]), "r"(B[0]), "r"(B[1]));
}
__device__ __forceinline__ void cp16(unsigned s, const void* g) {
    asm volatile("cp.async.cg.shared.global [%0], [%1], 16;" :: "r"(s), "l"(g));
}
__device__ __forceinline__ void cp_commit() { asm volatile("cp.async.commit_group;"); }
template<int N> __device__ __forceinline__ void cp_wait() {
    asm volatile("cp.async.wait_group %0;" :: "n"(N));
}
__device__ __forceinline__ void store_hilo(bf16* hi, bf16* lo, size_t idx,
                                           float a, float b) {
    __nv_bfloat162 h = __floats2bfloat162_rn(a, b);
    *(unsigned*)(hi + idx) = *reinterpret_cast<unsigned*>(&h);
    __nv_bfloat162 l = __floats2bfloat162_rn(a - __bfloat162float(h.x),
                                             b - __bfloat162float(h.y));
    *(unsigned*)(lo + idx) = *reinterpret_cast<unsigned*>(&l);
}
__device__ __forceinline__ float sigm(float x) { return 1.f / (1.f + expf(-x)); }

// epilogue smem layout (bf16 elements)
#define AP2 200
#define ACT_HI 0
#define ACT_LO 12800              // 64*AP2
#define WBOFF 25600               // 2*64*AP2
#define PARK_HI 43008             // WBOFF + 2*64*136
#define PARK_LO 55808             // PARK_HI + 64*AP2

// epilogue GEMM: act tile (hi/lo in smem) x W chunk (hi/lo), 3-product
template<int NBE>
__device__ __forceinline__ void epi3(
    bf16* sm, unsigned sbase, int aHi, int aLo, int Kd, int WP,
    const bf16* Whi, const bf16* Wlo, int Dout,
    int tid, int lane, int m0w, int n0e, float (&e)[2][NBE][4])
{
    #pragma unroll
    for (int i = 0; i < 2; i++)
        #pragma unroll
        for (int j = 0; j < NBE; j++)
            #pragma unroll
            for (int q = 0; q < 4; q++) e[i][j][q] = 0.f;
    const int wlo = WBOFF + 64 * WP;
    for (int k0 = 0; k0 < Kd; k0 += 64) {
        __syncthreads();
        const int du4 = Dout / 8;
        for (int it = tid; it < 64 * du4; it += 256) {
            int r = it / du4, c = (it % du4) * 8;
            cp16(sbase + 2u * (WBOFF + r * WP + c), Whi + (size_t)(k0 + r) * Dout + c);
            cp16(sbase + 2u * (wlo + r * WP + c),   Wlo + (size_t)(k0 + r) * Dout + c);
        }
        cp_commit(); cp_wait<0>();
        __syncthreads();
        #pragma unroll
        for (int ks = 0; ks < 4; ks++) {
            const int kk = ks * 16;
            unsigned ah[2][4], al[2][4];
            #pragma unroll
            for (int mi = 0; mi < 2; mi++) {
                unsigned row = m0w + mi * 16 + (lane & 15);
                unsigned col = k0 + kk + (lane >> 4) * 8;
                ldm_x4(ah[mi][0], ah[mi][1], ah[mi][2], ah[mi][3],
                       sbase + 2u * (aHi + row * AP2 + col));
                ldm_x4(al[mi][0], al[mi][1], al[mi][2], al[mi][3],
                       sbase + 2u * (aLo + row * AP2 + col));
            }
            unsigned bh[NBE][2], bl[NBE][2];
            if constexpr (NBE >= 2) {
                #pragma unroll
                for (int ni = 0; ni < NBE; ni += 2) {
                    unsigned row = kk + (lane & 15);
                    unsigned col = n0e + ni * 8 + (lane >> 4) * 8;
                    ldm_x4t(bh[ni][0], bh[ni][1], bh[ni+1][0], bh[ni+1][1],
                            sbase + 2u * (WBOFF + row * WP + col));
                    ldm_x4t(bl[ni][0], bl[ni][1], bl[ni+1][0], bl[ni+1][1],
                            sbase + 2u * (wlo + row * WP + col));
                }
            } else {
                unsigned row = kk + (lane & 15);
                ldm_x2t(bh[0][0], bh[0][1], sbase + 2u * (WBOFF + row * WP + n0e));
                ldm_x2t(bl[0][0], bl[0][1], sbase + 2u * (wlo + row * WP + n0e));
            }
            #pragma unroll
            for (int mi = 0; mi < 2; mi++)
                #pragma unroll
                for (int ni = 0; ni < NBE; ni++) {
                    mma_bf16(e[mi][ni], ah[mi], bh[ni]);
                    mma_bf16(e[mi][ni], ah[mi], bl[ni]);
                    mma_bf16(e[mi][ni], al[mi], bh[ni]);
                }
        }
    }
}

template<int NBX>
__device__ __forceinline__ void frag2act(const float (&a)[2][NBX][4], bf16* sm,
                                         int hiOff, int loOff, int goff,
                                         int m0, int n0, int lane)
{
    const int g4 = lane >> 2, t4 = lane & 3;
    #pragma unroll
    for (int mi = 0; mi < 2; mi++)
        #pragma unroll
        for (int ni = 0; ni < NBX; ni++) {
            int r0 = m0 + mi * 16 + g4;
            int c  = goff + n0 + ni * 8 + t4 * 2;
            store_hilo(sm + hiOff, sm + loOff, (size_t)r0 * AP2 + c,
                       a[mi][ni][0], a[mi][ni][1]);
            store_hilo(sm + hiOff, sm + loOff, (size_t)(r0 + 8) * AP2 + c,
                       a[mi][ni][2], a[mi][ni][3]);
        }
}

// ---------------------------------------------------------------------------
// agT: C = A[z] @ B[z] (M=K=1024, N=DN) + fused epilogue (DN=128).
// bf16 hi/lo x3, 3-stage cp.async, reg-pipelined fragments, PDL.
// ---------------------------------------------------------------------------
template<int DN>
__global__ void __launch_bounds__(256) agT_kernel(
    const bf16* __restrict__ Bhi_g, const bf16* __restrict__ Blo_g,
    int a_div, int c_perm, EpiArgs ep)
{
    constexpr int AP = 72, BP = DN + 8;
    constexpr int WN = DN / 4, NB = WN / 8;
    constexpr int A_LO = 64 * AP;
    constexpr int B_OFF = 2 * 64 * AP;
    constexpr int B_LO  = B_OFF + 64 * BP;
    constexpr int SBUF  = 2 * 64 * AP + 2 * 64 * BP;

    pdl_trigger();

    extern __shared__ bf16 sm[];
    const unsigned sbase = smem_u32(sm);

    const int tid = threadIdx.x, wid = tid >> 5, lane = tid & 31;
    const int mt = blockIdx.x;
    const int z  = blockIdx.z;
    const int a_idx = z / a_div;
    const int cz = c_perm ? ((z % a_div) * (gridDim.z / a_div) + a_idx) : z;
    const bf16* Bhi = Bhi_g + (size_t)z * NN * DN;
    const bf16* Blo = Blo_g + (size_t)z * NN * DN;
    const bf16* Ahi = g_Ahi + ((size_t)a_idx * NN + (size_t)mt * 64) * NN;
    const bf16* Alo = g_Alo + ((size_t)a_idx * NN + (size_t)mt * 64) * NN;

    const int wm = wid >> 2, wn = wid & 3;      // 2 x 4
    const int m0w = wm * 32, n0w = wn * WN;

    auto stageA = [&](int ch, int buf) {
        const int k0 = ch * 64;
        const unsigned db = sbase + 2u * (unsigned)(buf * SBUF);
        #pragma unroll
        for (int it = 0; it < 2; it++) {
            int item = tid + it * 256, r = item >> 3, c = item & 7;
            cp16(db + 2u * (r * AP + c * 8),        Ahi + (size_t)r * NN + k0 + c * 8);
            cp16(db + 2u * (A_LO + r * AP + c * 8), Alo + (size_t)r * NN + k0 + c * 8);
        }
    };
    auto stageB = [&](int ch, int buf) {
        const int k0 = ch * 64;
        const unsigned db = sbase + 2u * (unsigned)(buf * SBUF);
        #pragma unroll
        for (int it = 0; it < DN / 32; it++) {
            int item = tid + it * 256, r = item / (DN / 8), c = item % (DN / 8);
            cp16(db + 2u * (B_OFF + r * BP + c * 8), Bhi + (size_t)(k0 + r) * DN + c * 8);
            cp16(db + 2u * (B_LO  + r * BP + c * 8), Blo + (size_t)(k0 + r) * DN + c * 8);
        }
    };
    auto stage = [&](int ch, int buf) { stageA(ch, buf); stageB(ch, buf); cp_commit(); };

    float acc[2][NB][4];
    #pragma unroll
    for (int i = 0; i < 2; i++)
        #pragma unroll
        for (int j = 0; j < NB; j++)
            #pragma unroll
            for (int q = 0; q < 4; q++) acc[i][j][q] = 0.f;

    unsigned ah[2][2][4], al[2][2][4], bh[2][NB][2], bl[2][NB][2];
    auto ldfrag = [&](int ks, int pb, unsigned aB) {
        const int kk = ks * 16;
        #pragma unroll
        for (int mi = 0; mi < 2; mi++) {
            unsigned row = m0w + mi * 16 + (lane & 15);
            unsigned col = kk + (lane >> 4) * 8;
            ldm_x4(ah[pb][mi][0], ah[pb][mi][1], ah[pb][mi][2], ah[pb][mi][3],
                   aB + 2u * (row * AP + col));
            ldm_x4(al[pb][mi][0], al[pb][mi][1], al[pb][mi][2], al[pb][mi][3],
                   aB + 2u * (A_LO + row * AP + col));
        }
        #pragma unroll
        for (int ni = 0; ni < NB; ni += 2) {
            unsigned row = kk + (lane & 15);
            unsigned col = n0w + ni * 8 + (lane >> 4) * 8;
            ldm_x4t(bh[pb][ni][0], bh[pb][ni][1], bh[pb][ni+1][0], bh[pb][ni+1][1],
                    aB + 2u * (B_OFF + row * BP + col));
            ldm_x4t(bl[pb][ni][0], bl[pb][ni][1], bl[pb][ni+1][0], bl[pb][ni+1][1],
                    aB + 2u * (B_LO + row * BP + col));
        }
    };

    stageA(0, 0);
    stageA(1, 1);
    pdl_wait();
    stageB(0, 0); cp_commit();
    stageB(1, 1); cp_commit();

    for (int ch = 0; ch < 16; ch++) {
        const int buf = ch % 3;
        if (ch < 15) cp_wait<1>(); else cp_wait<0>();
        __syncthreads();
        if (ch <= 13) stage(ch + 2, (ch + 2) % 3);
        const unsigned aB = sbase + 2u * (unsigned)(buf * SBUF);
        ldfrag(0, 0, aB);
        #pragma unroll
        for (int ks = 0; ks < 4; ks++) {
            const int cur = ks & 1;
            if (ks < 3) ldfrag(ks + 1, cur ^ 1, aB);
            #pragma unroll
            for (int mi = 0; mi < 2; mi++)
                #pragma unroll
                for (int ni = 0; ni < NB; ni++) {
                    mma_bf16(acc[mi][ni], ah[cur][mi], bh[cur][ni]);
                    mma_bf16(acc[mi][ni], ah[cur][mi], bl[cur][ni]);
                    mma_bf16(acc[mi][ni], al[cur][mi], bh[cur][ni]);
                }
        }
    }

    const int g4 = lane >> 2, t4 = lane & 3;

    if (ep.emode == 0) {   // AX: bf16 hi/lo out
        bf16* ohi = g_AXhi + (size_t)cz * NN * DIN;
        bf16* olo = g_AXlo + (size_t)cz * NN * DIN;
        #pragma unroll
        for (int mi = 0; mi < 2; mi++)
            #pragma unroll
            for (int ni = 0; ni < NB; ni++) {
                int r0 = mt * 64 + m0w + mi * 16 + g4;
                int c  = n0w + ni * 8 + t4 * 2;
                store_hilo(ohi, olo, (size_t)r0 * DN + c, acc[mi][ni][0], acc[mi][ni][1]);
                store_hilo(ohi, olo, (size_t)(r0 + 8) * DN + c, acc[mi][ni][2], acc[mi][ni][3]);
            }
        return;
    }

    if constexpr (DN == 128) {
        __syncthreads();                        // stage buffers dead
        const int gr0 = mt * 64;
        const int n0e = wn * 32;

        if (ep.emode == 1) {                 // U = tanh(G@W+b), optional G1 store
            if (ep.g1) {
                #pragma unroll
                for (int mi = 0; mi < 2; mi++)
                    #pragma unroll
                    for (int ni = 0; ni < 4; ni++) {
                        int c = n0w + ni * 8 + t4 * 2;
                        size_t i0 = ((size_t)z * NN + gr0 + m0w + mi * 16 + g4) * DR + c;
                        *(float2*)(ep.g1 + i0) = make_float2(acc[mi][ni][0], acc[mi][ni][1]);
                        *(float2*)(ep.g1 + i0 + (size_t)8 * DR) =
                            make_float2(acc[mi][ni][2], acc[mi][ni][3]);
                    }
            }
            frag2act<4>(acc, sm, ACT_HI, ACT_LO, 0, m0w, n0w, lane);
            float e[2][4][4];
            epi3<4>(sm, sbase, ACT_HI, ACT_LO, 128, 136,
                    g_Whi + ep.w1, g_Wlo + ep.w1, 128, tid, lane, m0w, n0e, e);
            #pragma unroll
            for (int mi = 0; mi < 2; mi++)
                #pragma unroll
                for (int ni = 0; ni < 4; ni++) {
                    int c = n0e + ni * 8 + t4 * 2;
                    float2 bv = *(const float2*)(ep.b1 + c);
                    size_t i0 = ((size_t)z * NN + gr0 + m0w + mi * 16 + g4) * DR + c;
                    size_t i1 = i0 + (size_t)8 * DR;
                    store_hilo(ep.ohi, ep.olo, i0, tanhf(e[mi][ni][0] + bv.x),
                                                 tanhf(e[mi][ni][1] + bv.y));
                    store_hilo(ep.ohi, ep.olo, i1, tanhf(e[mi][ni][2] + bv.x),
                                                 tanhf(e[mi][ni][3] + bv.y));
                }
        } else if (ep.emode == 2) {          // HV1 + gates + head (fused)
            frag2act<4>(acc, sm, ACT_HI, ACT_LO, 0, m0w, n0w, lane);
            float e[2][4][4];
            epi3<4>(sm, sbase, ACT_HI, ACT_LO, 128, 136,
                    g_Whi + ep.w1, g_Wlo + ep.w1, 128, tid, lane, m0w, n0e, e);
            // pointwise: HV1 = H + DT*(e + b1) ; e <- HV1
            #pragma unroll
            for (int mi = 0; mi < 2; mi++)
                #pragma unroll
                for (int ni = 0; ni < 4; ni++) {
                    int c = n0e + ni * 8 + t4 * 2;
                    float2 bv = *(const float2*)(ep.b1 + c);
                    size_t i0 = ((size_t)z * NN + gr0 + m0w + mi * 16 + g4) * DR + c;
                    size_t i1 = i0 + (size_t)8 * DR;
                    float2 h0 = *(const float2*)(g_H + i0);
                    float2 h1 = *(const float2*)(g_H + i1);
                    float v0 = h0.x + (e[mi][ni][0] + bv.x) * DT_C;
                    float v1 = h0.y + (e[mi][ni][1] + bv.y) * DT_C;
                    float v2 = h1.x + (e[mi][ni][2] + bv.x) * DT_C;
                    float v3 = h1.y + (e[mi][ni][3] + bv.y) * DT_C;
                    *(float2*)(ep.of32 + i0) = make_float2(v0, v1);
                    *(float2*)(ep.of32 + i1) = make_float2(v2, v3);
                    if (ep.ohi) { store_hilo(ep.ohi, ep.olo, i0, v0, v1);
                                  store_hilo(ep.ohi, ep.olo, i1, v2, v3); }
                    e[mi][ni][0] = v0; e[mi][ni][1] = v1;
                    e[mi][ni][2] = v2; e[mi][ni][3] = v3;
                }
            const bool do_gates = (ep.zout != nullptr);
            const bool do_head  = (ep.dout != nullptr);
            if (do_gates || do_head) {
                __syncthreads();             // act reads (Wout GEMM) complete
                if (do_head)
                    frag2act<4>(e, sm, PARK_HI, PARK_LO, 0, m0w, n0e, lane);
                if (do_gates) {
                    // GHV1 = G1 + (HV1 - H)  -> act cols 64..191 (hi/lo)
                    #pragma unroll
                    for (int mi = 0; mi < 2; mi++)
                        #pragma unroll
                        for (int ni = 0; ni < 4; ni++) {
                            int c = n0e + ni * 8 + t4 * 2;
                            size_t i0 = ((size_t)z * NN + gr0 + m0w + mi * 16 + g4) * DR + c;
                            size_t i1 = i0 + (size_t)8 * DR;
                            float2 g10 = *(const float2*)(ep.g1 + i0);
                            float2 g11 = *(const float2*)(ep.g1 + i1);
                            float2 h0 = *(const float2*)(g_H + i0);
                            float2 h1 = *(const float2*)(g_H + i1);
                            int r0 = m0w + mi * 16 + g4;
                            store_hilo(sm + ACT_HI, sm + ACT_LO,
                                       (size_t)r0 * AP2 + 64 + c,
                                       g10.x + (e[mi][ni][0] - h0.x),
                                       g10.y + (e[mi][ni][1] - h0.y));
                            store_hilo(sm + ACT_HI, sm + ACT_LO,
                                       (size_t)(r0 + 8) * AP2 + 64 + c,
                                       g11.x + (e[mi][ni][2] - h1.x),
                                       g11.y + (e[mi][ni][3] - h1.y));
                        }
                    // AX prefix cols 0..63
                    const bf16* axh = g_AXhi + ((size_t)(ep.t * BB + z) * NN + gr0) * DIN;
                    const bf16* axl = g_AXlo + ((size_t)(ep.t * BB + z) * NN + gr0) * DIN;
                    #pragma unroll
                    for (int it = 0; it < 2; it++) {
                        int item = tid + it * 256, r = item >> 3, c = (item & 7) * 8;
                        *(uint4*)(sm + ACT_HI + (size_t)r * AP2 + c) =
                            *(const uint4*)(axh + (size_t)r * DIN + c);
                        *(uint4*)(sm + ACT_LO + (size_t)r * AP2 + c) =
                            *(const uint4*)(axl + (size_t)r * DIN + c);
                    }
                }
                if (do_gates) {
                    float ez[2][4][4];
                    epi3<4>(sm, sbase, ACT_HI, ACT_LO, 192, 136,
                            g_Whi + ep.w3, g_Wlo + ep.w3, 128, tid, lane, m0w, n0e, ez);
                    #pragma unroll
                    for (int mi = 0; mi < 2; mi++)
                        #pragma unroll
                        for (int ni = 0; ni < 4; ni++) {
                            int c = n0e + ni * 8 + t4 * 2;
                            float2 bv = *(const float2*)(ep.b3 + c);
                            size_t i0 = ((size_t)z * NN + gr0 + m0w + mi * 16 + g4) * DR + c;
                            size_t i1 = i0 + (size_t)8 * DR;
                            *(float2*)(ep.zout + i0) = make_float2(sigm(ez[mi][ni][0] + bv.x),
                                                                   sigm(ez[mi][ni][1] + bv.y));
                            *(float2*)(ep.zout + i1) = make_float2(sigm(ez[mi][ni][2] + bv.x),
                                                                   sigm(ez[mi][ni][3] + bv.y));
                        }
                    float er[2][4][4];
                    epi3<4>(sm, sbase, ACT_HI, ACT_LO, 192, 136,
                            g_Whi + ep.w4, g_Wlo + ep.w4, 128, tid, lane, m0w, n0e, er);
                    #pragma unroll
                    for (int mi = 0; mi < 2; mi++)
                        #pragma unroll
                        for (int ni = 0; ni < 4; ni++) {
                            int c = n0e + ni * 8 + t4 * 2;
                            float2 bv = *(const float2*)(ep.b4 + c);
                            size_t i0 = ((size_t)z * NN + gr0 + m0w + mi * 16 + g4) * DR + c;
                            size_t i1 = i0 + (size_t)8 * DR;
                            store_hilo(ep.rhhi, ep.rhlo, i0,
                                       sigm(er[mi][ni][0] + bv.x) * e[mi][ni][0],
                                       sigm(er[mi][ni][1] + bv.y) * e[mi][ni][1]);
                            store_hilo(ep.rhhi, ep.rhlo, i1,
                                       sigm(er[mi][ni][2] + bv.x) * e[mi][ni][2],
                                       sigm(er[mi][ni][3] + bv.y) * e[mi][ni][3]);
                        }
                }
                if (do_head) {
                    float e2[2][2][4];
                    epi3<2>(sm, sbase, PARK_HI, PARK_LO, 128, 72,
                            g_Whi + ep.w2, g_Wlo + ep.w2, 64, tid, lane, m0w, wn * 16, e2);
                    #pragma unroll
                    for (int mi = 0; mi < 2; mi++)
                        #pragma unroll
                        for (int ni = 0; ni < 2; ni++) {
                            int c = wn * 16 + ni * 8 + t4 * 2;
                            float2 bv = *(const float2*)(ep.b2 + c);
                            int r0 = gr0 + m0w + mi * 16 + g4;
                            size_t o0 = ((size_t)(z * (TT - 1) + ep.t - 1) * NN + r0) * DIN + c;
                            size_t o1 = o0 + (size_t)8 * DIN;
                            *(float2*)(ep.dout + o0) =
                                make_float2(e2[mi][ni][0] + bv.x, e2[mi][ni][1] + bv.y);
                            *(float2*)(ep.dout + o1) =
                                make_float2(e2[mi][ni][2] + bv.x, e2[mi][ni][3] + bv.y);
                        }
                }
            }
        } else {                             // emode 4: H = blend(tanh, Z, HV1, obs)
            frag2act<4>(acc, sm, ACT_HI, ACT_LO, 64, m0w, n0w, lane);
            const bf16* axh = g_AXhi + ((size_t)(ep.t * BB + z) * NN + gr0) * DIN;
            const bf16* axl = g_AXlo + ((size_t)(ep.t * BB + z) * NN + gr0) * DIN;
            #pragma unroll
            for (int it = 0; it < 2; it++) {
                int item = tid + it * 256, r = item >> 3, c = (item & 7) * 8;
                *(uint4*)(sm + ACT_HI + (size_t)r * AP2 + c) =
                    *(const uint4*)(axh + (size_t)r * DIN + c);
                *(uint4*)(sm + ACT_LO + (size_t)r * AP2 + c) =
                    *(const uint4*)(axl + (size_t)r * DIN + c);
            }
            float e[2][4][4];
            epi3<4>(sm, sbase, ACT_HI, ACT_LO, 192, 136,
                    g_Whi + ep.w1, g_Wlo + ep.w1, 128, tid, lane, m0w, n0e, e);
            const float ob = g_OBS[ep.t * BB + z];
            #pragma unroll
            for (int mi = 0; mi < 2; mi++)
                #pragma unroll
                for (int ni = 0; ni < 4; ni++) {
                    int c = n0e + ni * 8 + t4 * 2;
                    float2 bv = *(const float2*)(ep.b1 + c);
                    size_t i0 = ((size_t)z * NN + gr0 + m0w + mi * 16 + g4) * DR + c;
                    size_t i1 = i0 + (size_t)8 * DR;
                    float2 zz0 = *(const float2*)(g_Z + i0);
                    float2 zz1 = *(const float2*)(g_Z + i1);
                    float2 h0 = *(const float2*)(g_HV1 + i0);
                    float2 h1 = *(const float2*)(g_HV1 + i1);
                    float c0 = tanhf(e[mi][ni][0] + bv.x);
                    float c1 = tanhf(e[mi][ni][1] + bv.y);
                    float c2 = tanhf(e[mi][ni][2] + bv.x);
                    float c3 = tanhf(e[mi][ni][3] + bv.y);
                    float o0 = h0.x + (zz0.x * (c0 - h0.x)) * ob;
                    float o1 = h0.y + (zz0.y * (c1 - h0.y)) * ob;
                    float o2 = h1.x + (zz1.x * (c2 - h1.x)) * ob;
                    float o3 = h1.y + (zz1.y * (c3 - h1.y)) * ob;
                    *(float2*)(ep.of32 + i0) = make_float2(o0, o1);
                    *(float2*)(ep.of32 + i1) = make_float2(o2, o3);
                    store_hilo(ep.ohi, ep.olo, i0, o0, o1);
                    store_hilo(ep.ohi, ep.olo, i1, o2, o3);
                }
        }
    }
}

// --------------------------- small utility kernels -------------------------
__global__ void __launch_bounds__(256) convA_kernel(const float* __restrict__ A)
{
    const size_t r = blockIdx.x;
    const float* src = A + r * NN;
    bf16* dhi = g_Ahi + r * NN;
    bf16* dlo = g_Alo + r * NN;
    int i = threadIdx.x * 4;
    float4 v = *(const float4*)(src + i);
    float vv[4] = {v.x, v.y, v.z, v.w};
    #pragma unroll
    for (int j = 0; j < 4; j++) {
        bf16 h = __float2bfloat16(vv[j]);
        dhi[i+j] = h;
        dlo[i+j] = __float2bfloat16(vv[j] - __bfloat162float(h));
    }
}

__global__ void __launch_bounds__(256) convWall_kernel(
    const float* W0, const float* W1, const float* Wou, const float* Wz,
    const float* Wr, const float* Wh, const float* Wo)
{
    const float* W; long off; int n;
    switch (blockIdx.y) {
        case 0: W = W0;  off = OW0;   n = 16384; break;
        case 1: W = W1;  off = OW1;   n = 16384; break;
        case 2: W = Wou; off = OWOUT; n = 16384; break;
        case 3: W = Wz;  off = OWZ;   n = 24576; break;
        case 4: W = Wr;  off = OWR;   n = 24576; break;
        case 5: W = Wh;  off = OWH;   n = 24576; break;
        default: W = Wo; off = OWO;   n = 8192;  break;
    }
    int i = blockIdx.x * 256 + threadIdx.x;
    if (i >= n) return;
    float v = W[i];
    bf16 h = __float2bfloat16(v);
    g_Whi[off + i] = h;
    g_Wlo[off + i] = __float2bfloat16(v - __bfloat162float(h));
}

__global__ void __launch_bounds__(256) xmask_kernel(
    const float4* __restrict__ v, const float4* __restrict__ m)
{
    int i = blockIdx.x * 256 + threadIdx.x;
    float4 a = v[i], b = m[i];
    float x[4] = {a.x*b.x, a.y*b.y, a.z*b.z, a.w*b.w};
    bf16 hi[4], lo[4];
    #pragma unroll
    for (int j = 0; j < 4; j++) {
        hi[j] = __float2bfloat16(x[j]);
        lo[j] = __float2bfloat16(x[j] - __bfloat162float(hi[j]));
    }
    *(uint2*)&g_Xhi[(size_t)i*4] = *(uint2*)hi;
    *(uint2*)&g_Xlo[(size_t)i*4] = *(uint2*)lo;
}

__global__ void __launch_bounds__(256) inith_kernel(const float* __restrict__ h0)
{
    int i = blockIdx.x * 256 + threadIdx.x;
    float v = h0[i & (DR - 1)];
    g_H[i] = v;
    bf16 h = __float2bfloat16(v);
    g_Hhi[i] = h;
    g_Hlo[i] = __float2bfloat16(v - __bfloat162float(h));
}

__global__ void __launch_bounds__(256) obs_kernel(const float* __restrict__ masks)
{
    __shared__ float sh[256];
    int bt = blockIdx.x;
    const float* p = masks + (size_t)bt * (NN * DIN);
    float s = 0.f;
    for (int i = threadIdx.x; i < NN * DIN; i += 256) s += fabsf(p[i]);
    sh[threadIdx.x] = s; __syncthreads();
    for (int o = 128; o > 0; o >>= 1) {
        if (threadIdx.x < o) sh[threadIdx.x] += sh[threadIdx.x + o];
        __syncthreads();
    }
    if (threadIdx.x == 0) {
        int b = bt >> 5, t = bt & 31;
        g_OBS[t * BB + b] = (sh[0] > 1e-4f) ? 1.f : 0.f;
    }
}

// ------------------------------- launch ------------------------------------
extern "C" void kernel_launch(void* const* d_in, const int* in_sizes, int n_in,
                              void* d_out, int out_size)
{
    const float* values = (const float*)d_in[0];
    const float* masks  = (const float*)d_in[1];
    const float* A      = (const float*)d_in[2];
    const float* h0     = (const float*)d_in[3];
    const float* W0  = (const float*)d_in[4];  const float* b0v = (const float*)d_in[5];
    const float* W1  = (const float*)d_in[6];  const float* b1v = (const float*)d_in[7];
    const float* Wou = (const float*)d_in[8];  const float* bou = (const float*)d_in[9];
    const float* Wz  = (const float*)d_in[10]; const float* bz  = (const float*)d_in[11];
    const float* Wr  = (const float*)d_in[12]; const float* br  = (const float*)d_in[13];
    const float* Wh  = (const float*)d_in[14]; const float* bh  = (const float*)d_in[15];
    const float* Wo  = (const float*)d_in[16]; const float* bo  = (const float*)d_in[17];
    float* out = (float*)d_out;

    float *H, *HV1, *G1, *Z;
    bf16 *Xhi, *Xlo, *Hhi, *Hlo, *Uhi, *Ulo, *RHhi, *RHlo;
    cudaGetSymbolAddress((void**)&H,    g_H);
    cudaGetSymbolAddress((void**)&HV1,  g_HV1);
    cudaGetSymbolAddress((void**)&G1,   g_G1);
    cudaGetSymbolAddress((void**)&Z,    g_Z);
    cudaGetSymbolAddress((void**)&Xhi,  g_Xhi);  cudaGetSymbolAddress((void**)&Xlo,  g_Xlo);
    cudaGetSymbolAddress((void**)&Hhi,  g_Hhi);  cudaGetSymbolAddress((void**)&Hlo,  g_Hlo);
    cudaGetSymbolAddress((void**)&Uhi,  g_Uhi);  cudaGetSymbolAddress((void**)&Ulo,  g_Ulo);
    cudaGetSymbolAddress((void**)&RHhi, g_RHhi); cudaGetSymbolAddress((void**)&RHlo, g_RHlo);

    const int SM128 = 3 * (2*64*72 + 2*64*136) * 2;   // 159744 B
    const int SM64  = 3 * (2*64*72 + 2*64*72)  * 2;   // 110592 B
    cudaFuncSetAttribute(agT_kernel<128>, cudaFuncAttributeMaxDynamicSharedMemorySize, SM128);
    cudaFuncSetAttribute(agT_kernel<64>,  cudaFuncAttributeMaxDynamicSharedMemorySize, SM64);

    // --- precompute ---
    convA_kernel<<<BB*NN, 256>>>(A);
    convWall_kernel<<<dim3(96, 7), 256>>>(W0, W1, Wou, Wz, Wr, Wh, Wo);
    xmask_kernel<<<(BB*TT*NN*DIN)/4/256, 256>>>(
        (const float4*)values, (const float4*)masks);
    obs_kernel<<<BB*TT, 256>>>(masks);
    inith_kernel<<<(BB*NN*DR)/256, 256>>>(h0);

    cudaLaunchAttribute pdlAttr[1];
    pdlAttr[0].id = cudaLaunchAttributeProgrammaticStreamSerialization;
    pdlAttr[0].val.programmaticStreamSerializationAllowed = 1;

    EpiArgs ax{0, 0, 0, 0, 0, 0, nullptr, nullptr, nullptr, nullptr,
               nullptr, nullptr, nullptr, nullptr, nullptr, nullptr, nullptr, nullptr};
    {
        cudaLaunchConfig_t cfg = {};
        cfg.gridDim = dim3(16, 1, BB*TT);
        cfg.blockDim = dim3(256, 1, 1);
        cfg.dynamicSmemBytes = SM64;
        cfg.stream = 0;
        cfg.attrs = pdlAttr;
        cfg.numAttrs = 1;
        cudaLaunchKernelEx(&cfg, agT_kernel<DIN>, (const bf16*)Xhi, (const bf16*)Xlo, TT, 1, ax);
    }

    auto AGE = [&](const bf16* bhi, const bf16* blo, EpiArgs ep) {
        cudaLaunchConfig_t cfg = {};
        cfg.gridDim = dim3(16, 1, BB);
        cfg.blockDim = dim3(256, 1, 1);
        cfg.dynamicSmemBytes = SM128;
        cfg.stream = 0;
        cfg.attrs = pdlAttr;
        cfg.numAttrs = 1;
        cudaLaunchKernelEx(&cfg, agT_kernel<DR>, bhi, blo, 1, 0, ep);
    };

    // ODE chain for step t (t=-1: init step writing H; else writes HV1 + gates/head)
    auto ODE = [&](int t) {
        bool gates = (t >= 0 && t < TT - 1);
        bool head  = (t >= 1);
        float* tf  = (t < 0) ? H : HV1;
        bf16* thi  = (t < 0) ? Hhi : nullptr;
        bf16* tlo  = (t < 0) ? Hlo : nullptr;
        AGE(Hhi, Hlo, {1, t, OW0, 0, 0, 0, b0v, nullptr, nullptr, nullptr,
                       nullptr, G1, nullptr, nullptr, Uhi, Ulo, nullptr, nullptr});
        AGE(Uhi, Ulo, {1, t, OW1, 0, 0, 0, b1v, nullptr, nullptr, nullptr,
                       nullptr, nullptr, nullptr, nullptr, Uhi, Ulo, nullptr, nullptr});
        AGE(Uhi, Ulo, {2, t, OWOUT, OWO, OWZ, OWR, bou, bo, bz, br,
                       tf, G1, gates ? Z : nullptr, head ? out : nullptr,
                       thi, tlo, RHhi, RHlo});
    };

    // iteration 0: h = h + ode(h)*DT
    ODE(-1);

    for (int t = 0; t < TT; t++) {
        ODE(t);                                   // HV1 + gates (t<31) + head (t>=1)
        if (t < TT - 1)
            AGE(RHhi, RHlo, {4, t, OWH, 0, 0, 0, bh, nullptr, nullptr, nullptr,
                             H, nullptr, nullptr, nullptr, Hhi, Hlo, nullptr, nullptr});
    }
}

// round 14
// speedup vs baseline: 1.2042x; 1.0655x over previous
#include <cuda_runtime.h>
#include <cuda_bf16.h>
#include <cstdint>
#include <math.h>

#define BB 8
#define TT 32
#define NN 1024
#define DIN 64
#define DR 128
#define DT_C 0.25f
typedef __nv_bfloat16 bf16;

#define OW0 0
#define OW1 16384
#define OWOUT 32768
#define OWZ 49152
#define OWR 73728
#define OWH 98304
#define OWO 122880

// ------------------------- device scratch (no allocs) ----------------------
__device__ bf16 g_Ahi[(size_t)BB*NN*NN];
__device__ bf16 g_Alo[(size_t)BB*NN*NN];
__device__ bf16 g_Xhi[(size_t)BB*TT*NN*DIN];
__device__ bf16 g_Xlo[(size_t)BB*TT*NN*DIN];
__device__ bf16 g_AXhi[(size_t)TT*BB*NN*DIN];
__device__ bf16 g_AXlo[(size_t)TT*BB*NN*DIN];
__device__ float g_H[BB*NN*DR];
__device__ bf16 g_Hhi[BB*NN*DR], g_Hlo[BB*NN*DR];
__device__ float g_HV1[BB*NN*DR];
__device__ float g_G1[BB*NN*DR];
__device__ bf16 g_Uhi[BB*NN*DR], g_Ulo[BB*NN*DR];
__device__ bf16 g_RHhi[BB*NN*DR], g_RHlo[BB*NN*DR];
__device__ float g_Z[BB*NN*DR];
__device__ float g_OBS[TT*BB];
__device__ bf16 g_Whi[131072], g_Wlo[131072];

struct EpiArgs {
    int emode, t;        // 0 AX, 1 tanh(+G1 store), 2 hv1+gates+head, 4 Hblend
    long w1, w2, w3, w4;
    const float *b1, *b2, *b3, *b4;
    float *of32, *g1, *zout, *dout;
    bf16 *ohi, *olo, *rhhi, *rhlo;
};

// ----------------------------- PTX helpers ---------------------------------
__device__ __forceinline__ void pdl_trigger() {
    asm volatile("griddepcontrol.launch_dependents;" ::: "memory");
}
__device__ __forceinline__ void pdl_wait() {
    asm volatile("griddepcontrol.wait;" ::: "memory");
}
__device__ __forceinline__ unsigned smem_u32(const void* p) {
    unsigned a;
    asm("{ .reg .u64 t; cvta.to.shared.u64 t, %1; cvt.u32.u64 %0, t; }"
        : "=r"(a) : "l"(p));
    return a;
}
__device__ __forceinline__ void ldm_x4(unsigned& r0, unsigned& r1,
                                       unsigned& r2, unsigned& r3, unsigned a) {
    asm volatile("ldmatrix.sync.aligned.m8n8.x4.shared.b16 {%0,%1,%2,%3}, [%4];"
                 : "=r"(r0), "=r"(r1), "=r"(r2), "=r"(r3) : "r"(a));
}
__device__ __forceinline__ void ldm_x2t(unsigned& r0, unsigned& r1, unsigned a) {
    asm volatile("ldmatrix.sync.aligned.m8n8.x2.trans.shared.b16 {%0,%1}, [%2];"
                 : "=r"(r0), "=r"(r1) : "r"(a));
}
__device__ __forceinline__ void ldm_x4t(unsigned& r0, unsigned& r1,
                                        unsigned& r2, unsigned& r3, unsigned a) {
    asm volatile("ldmatrix.sync.aligned.m8n8.x4.trans.shared.b16 {%0,%1,%2,%3}, [%4];"
                 : "=r"(r0), "=r"(r1), "=r"(r2), "=r"(r3) : "r"(a));
}
__device__ __forceinline__ void mma_bf16(float* c, const unsigned* A, const unsigned* B) {
    asm volatile(
        "mma.sync.aligned.m16n8k16.row.col.f32.bf16.bf16.f32 "
        "{%0,%1,%2,%3}, {%4,%5,%6,%7}, {%8,%9}, {%0,%1,%2,%3};"
        : "+f"(c[0]), "+f"(c[1]), "+f"(c[2]), "+f"(c[3])
        : "r"(A[0]), "r"(A[1]), "r"(A[2]), "r"(A[3]), "r"(B[0]), "r"(B[1]));
}
__device__ __forceinline__ void cp16(unsigned s, const void* g) {
    asm volatile("cp.async.cg.shared.global [%0], [%1], 16;" :: "r"(s), "l"(g));
}
__device__ __forceinline__ void cp_commit() { asm volatile("cp.async.commit_group;"); }
template<int N> __device__ __forceinline__ void cp_wait() {
    asm volatile("cp.async.wait_group %0;" :: "n"(N));
}
__device__ __forceinline__ void store_hilo(bf16* hi, bf16* lo, size_t idx,
                                           float a, float b) {
    __nv_bfloat162 h = __floats2bfloat162_rn(a, b);
    *(unsigned*)(hi + idx) = *reinterpret_cast<unsigned*>(&h);
    __nv_bfloat162 l = __floats2bfloat162_rn(a - __bfloat162float(h.x),
                                             b - __bfloat162float(h.y));
    *(unsigned*)(lo + idx) = *reinterpret_cast<unsigned*>(&l);
}
__device__ __forceinline__ float sigm(float x) {
    return __fdividef(1.f, 1.f + __expf(-x));
}
__device__ __forceinline__ float ftanh(float x) {           // NaN-safe both tails
    return 1.f - __fdividef(2.f, __expf(2.f * x) + 1.f);
}

// epilogue smem layout (bf16 elements)
#define AP2 200
#define ACT_HI 0
#define ACT_LO 12800              // 64*AP2
#define WBOFF 25600               // 2*64*AP2
#define WBSZ 17408                // 2*64*136 (one W hi+lo buffer)
#define PARK_HI 60416             // WBOFF + 2*WBSZ
#define PARK_LO 73216             // PARK_HI + 64*AP2  (end 86016 elem = 172032 B)

// pipelined single-W epilogue GEMM (3-product, 2 W buffers)
template<int NBE>
__device__ __forceinline__ void epi3(
    bf16* sm, unsigned sbase, int aHi, int aLo, int Kd, int WP,
    const bf16* Whi, const bf16* Wlo, int Dout,
    int tid, int lane, int m0w, int n0e, float (&e)[2][NBE][4])
{
    #pragma unroll
    for (int i = 0; i < 2; i++)
        #pragma unroll
        for (int j = 0; j < NBE; j++)
            #pragma unroll
            for (int q = 0; q < 4; q++) e[i][j][q] = 0.f;
    const int du4 = Dout / 8;
    auto stW = [&](int k0, int wb) {
        const int base = WBOFF + wb * WBSZ;
        for (int it = tid; it < 64 * du4; it += 256) {
            int r = it / du4, c = (it % du4) * 8;
            cp16(sbase + 2u * (base + r * WP + c), Whi + (size_t)(k0 + r) * Dout + c);
            cp16(sbase + 2u * (base + 64 * WP + r * WP + c),
                 Wlo + (size_t)(k0 + r) * Dout + c);
        }
        cp_commit();
    };
    const int NC = Kd / 64;
    __syncthreads();                  // prior act writes + W-buffer reuse guard
    stW(0, 0);
    for (int c = 0; c < NC; c++) {
        cp_wait<0>();
        __syncthreads();
        if (c + 1 < NC) stW((c + 1) * 64, (c + 1) & 1);
        const int wb = WBOFF + (c & 1) * WBSZ;
        const int wl = wb + 64 * WP;
        #pragma unroll
        for (int ks = 0; ks < 4; ks++) {
            const int kk = ks * 16;
            unsigned ah[2][4], al[2][4];
            #pragma unroll
            for (int mi = 0; mi < 2; mi++) {
                unsigned row = m0w + mi * 16 + (lane & 15);
                unsigned col = c * 64 + kk + (lane >> 4) * 8;
                ldm_x4(ah[mi][0], ah[mi][1], ah[mi][2], ah[mi][3],
                       sbase + 2u * (aHi + row * AP2 + col));
                ldm_x4(al[mi][0], al[mi][1], al[mi][2], al[mi][3],
                       sbase + 2u * (aLo + row * AP2 + col));
            }
            unsigned bh[NBE][2], bl[NBE][2];
            if constexpr (NBE >= 2) {
                #pragma unroll
                for (int ni = 0; ni < NBE; ni += 2) {
                    unsigned row = kk + (lane & 15);
                    unsigned col = n0e + ni * 8 + (lane >> 4) * 8;
                    ldm_x4t(bh[ni][0], bh[ni][1], bh[ni+1][0], bh[ni+1][1],
                            sbase + 2u * (wb + row * WP + col));
                    ldm_x4t(bl[ni][0], bl[ni][1], bl[ni+1][0], bl[ni+1][1],
                            sbase + 2u * (wl + row * WP + col));
                }
            } else {
                unsigned row = kk + (lane & 15);
                ldm_x2t(bh[0][0], bh[0][1], sbase + 2u * (wb + row * WP + n0e));
                ldm_x2t(bl[0][0], bl[0][1], sbase + 2u * (wl + row * WP + n0e));
            }
            #pragma unroll
            for (int mi = 0; mi < 2; mi++)
                #pragma unroll
                for (int ni = 0; ni < NBE; ni++) {
                    mma_bf16(e[mi][ni], ah[mi], bh[ni]);
                    mma_bf16(e[mi][ni], ah[mi], bl[ni]);
                    mma_bf16(e[mi][ni], al[mi], bh[ni]);
                }
        }
    }
}

// dual-W epilogue GEMM (Z and R gates share the act tile; Dout=128)
__device__ __forceinline__ void epi3dual(
    bf16* sm, unsigned sbase, int Kd,
    const bf16* W0h, const bf16* W0l, const bf16* W1h, const bf16* W1l,
    int tid, int lane, int m0w, int n0e,
    float (&e0)[2][4][4], float (&e1)[2][4][4])
{
    #pragma unroll
    for (int i = 0; i < 2; i++)
        #pragma unroll
        for (int j = 0; j < 4; j++)
            #pragma unroll
            for (int q = 0; q < 4; q++) { e0[i][j][q] = 0.f; e1[i][j][q] = 0.f; }
    constexpr int WP = 136;
    auto stW = [&](const bf16* Whi, const bf16* Wlo, int k0, int wb) {
        const int base = WBOFF + wb * WBSZ;
        for (int it = tid; it < 64 * 16; it += 256) {
            int r = it / 16, c = (it % 16) * 8;
            cp16(sbase + 2u * (base + r * WP + c), Whi + (size_t)(k0 + r) * 128 + c);
            cp16(sbase + 2u * (base + 64 * WP + r * WP + c),
                 Wlo + (size_t)(k0 + r) * 128 + c);
        }
    };
    const int NC = Kd / 64;
    for (int c = 0; c < NC; c++) {
        __syncthreads();
        stW(W0h, W0l, c * 64, 0);
        stW(W1h, W1l, c * 64, 1);
        cp_commit();
        cp_wait<0>();
        __syncthreads();
        #pragma unroll
        for (int ks = 0; ks < 4; ks++) {
            const int kk = ks * 16;
            unsigned ah[2][4], al[2][4];
            #pragma unroll
            for (int mi = 0; mi < 2; mi++) {
                unsigned row = m0w + mi * 16 + (lane & 15);
                unsigned col = c * 64 + kk + (lane >> 4) * 8;
                ldm_x4(ah[mi][0], ah[mi][1], ah[mi][2], ah[mi][3],
                       sbase + 2u * (ACT_HI + row * AP2 + col));
                ldm_x4(al[mi][0], al[mi][1], al[mi][2], al[mi][3],
                       sbase + 2u * (ACT_LO + row * AP2 + col));
            }
            #pragma unroll
            for (int w = 0; w < 2; w++) {
                const int wb = WBOFF + w * WBSZ, wl = wb + 64 * WP;
                unsigned bh[4][2], bl[4][2];
                #pragma unroll
                for (int ni = 0; ni < 4; ni += 2) {
                    unsigned row = kk + (lane & 15);
                    unsigned col = n0e + ni * 8 + (lane >> 4) * 8;
                    ldm_x4t(bh[ni][0], bh[ni][1], bh[ni+1][0], bh[ni+1][1],
                            sbase + 2u * (wb + row * WP + col));
                    ldm_x4t(bl[ni][0], bl[ni][1], bl[ni+1][0], bl[ni+1][1],
                            sbase + 2u * (wl + row * WP + col));
                }
                #pragma unroll
                for (int mi = 0; mi < 2; mi++)
                    #pragma unroll
                    for (int ni = 0; ni < 4; ni++) {
                        float* ee = w ? e1[mi][ni] : e0[mi][ni];
                        mma_bf16(ee, ah[mi], bh[ni]);
                        mma_bf16(ee, ah[mi], bl[ni]);
                        mma_bf16(ee, al[mi], bh[ni]);
                    }
            }
        }
    }
}

template<int NBX>
__device__ __forceinline__ void frag2act(const float (&a)[2][NBX][4], bf16* sm,
                                         int hiOff, int loOff, int goff,
                                         int m0, int n0, int lane)
{
    const int g4 = lane >> 2, t4 = lane & 3;
    #pragma unroll
    for (int mi = 0; mi < 2; mi++)
        #pragma unroll
        for (int ni = 0; ni < NBX; ni++) {
            int r0 = m0 + mi * 16 + g4;
            int c  = goff + n0 + ni * 8 + t4 * 2;
            store_hilo(sm + hiOff, sm + loOff, (size_t)r0 * AP2 + c,
                       a[mi][ni][0], a[mi][ni][1]);
            store_hilo(sm + hiOff, sm + loOff, (size_t)(r0 + 8) * AP2 + c,
                       a[mi][ni][2], a[mi][ni][3]);
        }
}

// ---------------------------------------------------------------------------
// agT: C = A[z] @ B[z] (M=K=1024, N=DN) + fused epilogue (DN=128).
// ---------------------------------------------------------------------------
template<int DN>
__global__ void __launch_bounds__(256) agT_kernel(
    const bf16* __restrict__ Bhi_g, const bf16* __restrict__ Blo_g,
    int a_div, int c_perm, EpiArgs ep)
{
    constexpr int AP = 72, BP = DN + 8;
    constexpr int WN = DN / 4, NB = WN / 8;
    constexpr int A_LO = 64 * AP;
    constexpr int B_OFF = 2 * 64 * AP;
    constexpr int B_LO  = B_OFF + 64 * BP;
    constexpr int SBUF  = 2 * 64 * AP + 2 * 64 * BP;

    pdl_trigger();

    extern __shared__ bf16 sm[];
    const unsigned sbase = smem_u32(sm);

    const int tid = threadIdx.x, wid = tid >> 5, lane = tid & 31;
    const int mt = blockIdx.x;
    const int z  = blockIdx.z;
    const int a_idx = z / a_div;
    const int cz = c_perm ? ((z % a_div) * (gridDim.z / a_div) + a_idx) : z;
    const bf16* Bhi = Bhi_g + (size_t)z * NN * DN;
    const bf16* Blo = Blo_g + (size_t)z * NN * DN;
    const bf16* Ahi = g_Ahi + ((size_t)a_idx * NN + (size_t)mt * 64) * NN;
    const bf16* Alo = g_Alo + ((size_t)a_idx * NN + (size_t)mt * 64) * NN;

    const int wm = wid >> 2, wn = wid & 3;
    const int m0w = wm * 32, n0w = wn * WN;

    auto stageA = [&](int ch, int buf) {
        const int k0 = ch * 64;
        const unsigned db = sbase + 2u * (unsigned)(buf * SBUF);
        #pragma unroll
        for (int it = 0; it < 2; it++) {
            int item = tid + it * 256, r = item >> 3, c = item & 7;
            cp16(db + 2u * (r * AP + c * 8),        Ahi + (size_t)r * NN + k0 + c * 8);
            cp16(db + 2u * (A_LO + r * AP + c * 8), Alo + (size_t)r * NN + k0 + c * 8);
        }
    };
    auto stageB = [&](int ch, int buf) {
        const int k0 = ch * 64;
        const unsigned db = sbase + 2u * (unsigned)(buf * SBUF);
        #pragma unroll
        for (int it = 0; it < DN / 32; it++) {
            int item = tid + it * 256, r = item / (DN / 8), c = item % (DN / 8);
            cp16(db + 2u * (B_OFF + r * BP + c * 8), Bhi + (size_t)(k0 + r) * DN + c * 8);
            cp16(db + 2u * (B_LO  + r * BP + c * 8), Blo + (size_t)(k0 + r) * DN + c * 8);
        }
    };
    auto stage = [&](int ch, int buf) { stageA(ch, buf); stageB(ch, buf); cp_commit(); };

    float acc[2][NB][4];
    #pragma unroll
    for (int i = 0; i < 2; i++)
        #pragma unroll
        for (int j = 0; j < NB; j++)
            #pragma unroll
            for (int q = 0; q < 4; q++) acc[i][j][q] = 0.f;

    unsigned ah[2][2][4], al[2][2][4], bh[2][NB][2], bl[2][NB][2];
    auto ldfrag = [&](int ks, int pb, unsigned aB) {
        const int kk = ks * 16;
        #pragma unroll
        for (int mi = 0; mi < 2; mi++) {
            unsigned row = m0w + mi * 16 + (lane & 15);
            unsigned col = kk + (lane >> 4) * 8;
            ldm_x4(ah[pb][mi][0], ah[pb][mi][1], ah[pb][mi][2], ah[pb][mi][3],
                   aB + 2u * (row * AP + col));
            ldm_x4(al[pb][mi][0], al[pb][mi][1], al[pb][mi][2], al[pb][mi][3],
                   aB + 2u * (A_LO + row * AP + col));
        }
        #pragma unroll
        for (int ni = 0; ni < NB; ni += 2) {
            unsigned row = kk + (lane & 15);
            unsigned col = n0w + ni * 8 + (lane >> 4) * 8;
            ldm_x4t(bh[pb][ni][0], bh[pb][ni][1], bh[pb][ni+1][0], bh[pb][ni+1][1],
                    aB + 2u * (B_OFF + row * BP + col));
            ldm_x4t(bl[pb][ni][0], bl[pb][ni][1], bl[pb][ni+1][0], bl[pb][ni+1][1],
                    aB + 2u * (B_LO + row * BP + col));
        }
    };

    stageA(0, 0);
    stageA(1, 1);
    pdl_wait();
    stageB(0, 0); cp_commit();
    stageB(1, 1); cp_commit();

    for (int ch = 0; ch < 16; ch++) {
        const int buf = ch % 3;
        if (ch < 15) cp_wait<1>(); else cp_wait<0>();
        __syncthreads();
        if (ch <= 13) stage(ch + 2, (ch + 2) % 3);
        const unsigned aB = sbase + 2u * (unsigned)(buf * SBUF);
        ldfrag(0, 0, aB);
        #pragma unroll
        for (int ks = 0; ks < 4; ks++) {
            const int cur = ks & 1;
            if (ks < 3) ldfrag(ks + 1, cur ^ 1, aB);
            #pragma unroll
            for (int mi = 0; mi < 2; mi++)
                #pragma unroll
                for (int ni = 0; ni < NB; ni++) {
                    mma_bf16(acc[mi][ni], ah[cur][mi], bh[cur][ni]);
                    mma_bf16(acc[mi][ni], ah[cur][mi], bl[cur][ni]);
                    mma_bf16(acc[mi][ni], al[cur][mi], bh[cur][ni]);
                }
        }
    }

    const int g4 = lane >> 2, t4 = lane & 3;

    if (ep.emode == 0) {
        bf16* ohi = g_AXhi + (size_t)cz * NN * DIN;
        bf16* olo = g_AXlo + (size_t)cz * NN * DIN;
        #pragma unroll
        for (int mi = 0; mi < 2; mi++)
            #pragma unroll
            for (int ni = 0; ni < NB; ni++) {
                int r0 = mt * 64 + m0w + mi * 16 + g4;
                int c  = n0w + ni * 8 + t4 * 2;
                store_hilo(ohi, olo, (size_t)r0 * DN + c, acc[mi][ni][0], acc[mi][ni][1]);
                store_hilo(ohi, olo, (size_t)(r0 + 8) * DN + c, acc[mi][ni][2], acc[mi][ni][3]);
            }
        return;
    }

    if constexpr (DN == 128) {
        __syncthreads();
        const int gr0 = mt * 64;
        const int n0e = wn * 32;

        if (ep.emode == 1) {                 // U = tanh(G@W+b), optional G1 store
            if (ep.g1) {
                #pragma unroll
                for (int mi = 0; mi < 2; mi++)
                    #pragma unroll
                    for (int ni = 0; ni < 4; ni++) {
                        int c = n0w + ni * 8 + t4 * 2;
                        size_t i0 = ((size_t)z * NN + gr0 + m0w + mi * 16 + g4) * DR + c;
                        *(float2*)(ep.g1 + i0) = make_float2(acc[mi][ni][0], acc[mi][ni][1]);
                        *(float2*)(ep.g1 + i0 + (size_t)8 * DR) =
                            make_float2(acc[mi][ni][2], acc[mi][ni][3]);
                    }
            }
            frag2act<4>(acc, sm, ACT_HI, ACT_LO, 0, m0w, n0w, lane);
            float e[2][4][4];
            epi3<4>(sm, sbase, ACT_HI, ACT_LO, 128, 136,
                    g_Whi + ep.w1, g_Wlo + ep.w1, 128, tid, lane, m0w, n0e, e);
            #pragma unroll
            for (int mi = 0; mi < 2; mi++)
                #pragma unroll
                for (int ni = 0; ni < 4; ni++) {
                    int c = n0e + ni * 8 + t4 * 2;
                    float2 bv = *(const float2*)(ep.b1 + c);
                    size_t i0 = ((size_t)z * NN + gr0 + m0w + mi * 16 + g4) * DR + c;
                    size_t i1 = i0 + (size_t)8 * DR;
                    store_hilo(ep.ohi, ep.olo, i0, ftanh(e[mi][ni][0] + bv.x),
                                                 ftanh(e[mi][ni][1] + bv.y));
                    store_hilo(ep.ohi, ep.olo, i1, ftanh(e[mi][ni][2] + bv.x),
                                                 ftanh(e[mi][ni][3] + bv.y));
                }
        } else if (ep.emode == 2) {          // HV1 + gates + head (fused)
            frag2act<4>(acc, sm, ACT_HI, ACT_LO, 0, m0w, n0w, lane);
            float e[2][4][4];
            epi3<4>(sm, sbase, ACT_HI, ACT_LO, 128, 136,
                    g_Whi + ep.w1, g_Wlo + ep.w1, 128, tid, lane, m0w, n0e, e);
            #pragma unroll
            for (int mi = 0; mi < 2; mi++)
                #pragma unroll
                for (int ni = 0; ni < 4; ni++) {
                    int c = n0e + ni * 8 + t4 * 2;
                    float2 bv = *(const float2*)(ep.b1 + c);
                    size_t i0 = ((size_t)z * NN + gr0 + m0w + mi * 16 + g4) * DR + c;
                    size_t i1 = i0 + (size_t)8 * DR;
                    float2 h0 = *(const float2*)(g_H + i0);
                    float2 h1 = *(const float2*)(g_H + i1);
                    float v0 = h0.x + (e[mi][ni][0] + bv.x) * DT_C;
                    float v1 = h0.y + (e[mi][ni][1] + bv.y) * DT_C;
                    float v2 = h1.x + (e[mi][ni][2] + bv.x) * DT_C;
                    float v3 = h1.y + (e[mi][ni][3] + bv.y) * DT_C;
                    *(float2*)(ep.of32 + i0) = make_float2(v0, v1);
                    *(float2*)(ep.of32 + i1) = make_float2(v2, v3);
                    if (ep.ohi) { store_hilo(ep.ohi, ep.olo, i0, v0, v1);
                                  store_hilo(ep.ohi, ep.olo, i1, v2, v3); }
                    e[mi][ni][0] = v0; e[mi][ni][1] = v1;
                    e[mi][ni][2] = v2; e[mi][ni][3] = v3;
                }
            const bool do_gates = (ep.zout != nullptr);
            const bool do_head  = (ep.dout != nullptr);
            if (do_gates || do_head) {
                __syncthreads();
                if (do_head)
                    frag2act<4>(e, sm, PARK_HI, PARK_LO, 0, m0w, n0e, lane);
                if (do_gates) {
                    // GHV1 = G1 + (HV1 - H) -> act cols 64..191
                    #pragma unroll
                    for (int mi = 0; mi < 2; mi++)
                        #pragma unroll
                        for (int ni = 0; ni < 4; ni++) {
                            int c = n0e + ni * 8 + t4 * 2;
                            size_t i0 = ((size_t)z * NN + gr0 + m0w + mi * 16 + g4) * DR + c;
                            size_t i1 = i0 + (size_t)8 * DR;
                            float2 g10 = *(const float2*)(ep.g1 + i0);
                            float2 g11 = *(const float2*)(ep.g1 + i1);
                            float2 h0 = *(const float2*)(g_H + i0);
                            float2 h1 = *(const float2*)(g_H + i1);
                            int r0 = m0w + mi * 16 + g4;
                            store_hilo(sm + ACT_HI, sm + ACT_LO,
                                       (size_t)r0 * AP2 + 64 + c,
                                       g10.x + (e[mi][ni][0] - h0.x),
                                       g10.y + (e[mi][ni][1] - h0.y));
                            store_hilo(sm + ACT_HI, sm + ACT_LO,
                                       (size_t)(r0 + 8) * AP2 + 64 + c,
                                       g11.x + (e[mi][ni][2] - h1.x),
                                       g11.y + (e[mi][ni][3] - h1.y));
                        }
                    const bf16* axh = g_AXhi + ((size_t)(ep.t * BB + z) * NN + gr0) * DIN;
                    const bf16* axl = g_AXlo + ((size_t)(ep.t * BB + z) * NN + gr0) * DIN;
                    #pragma unroll
                    for (int it = 0; it < 2; it++) {
                        int item = tid + it * 256, r = item >> 3, c = (item & 7) * 8;
                        *(uint4*)(sm + ACT_HI + (size_t)r * AP2 + c) =
                            *(const uint4*)(axh + (size_t)r * DIN + c);
                        *(uint4*)(sm + ACT_LO + (size_t)r * AP2 + c) =
                            *(const uint4*)(axl + (size_t)r * DIN + c);
                    }
                    float ez[2][4][4], er[2][4][4];
                    epi3dual(sm, sbase, 192,
                             g_Whi + ep.w3, g_Wlo + ep.w3,
                             g_Whi + ep.w4, g_Wlo + ep.w4,
                             tid, lane, m0w, n0e, ez, er);
                    #pragma unroll
                    for (int mi = 0; mi < 2; mi++)
                        #pragma unroll
                        for (int ni = 0; ni < 4; ni++) {
                            int c = n0e + ni * 8 + t4 * 2;
                            float2 bz2 = *(const float2*)(ep.b3 + c);
                            float2 br2 = *(const float2*)(ep.b4 + c);
                            size_t i0 = ((size_t)z * NN + gr0 + m0w + mi * 16 + g4) * DR + c;
                            size_t i1 = i0 + (size_t)8 * DR;
                            *(float2*)(ep.zout + i0) =
                                make_float2(sigm(ez[mi][ni][0] + bz2.x),
                                            sigm(ez[mi][ni][1] + bz2.y));
                            *(float2*)(ep.zout + i1) =
                                make_float2(sigm(ez[mi][ni][2] + bz2.x),
                                            sigm(ez[mi][ni][3] + bz2.y));
                            store_hilo(ep.rhhi, ep.rhlo, i0,
                                       sigm(er[mi][ni][0] + br2.x) * e[mi][ni][0],
                                       sigm(er[mi][ni][1] + br2.y) * e[mi][ni][1]);
                            store_hilo(ep.rhhi, ep.rhlo, i1,
                                       sigm(er[mi][ni][2] + br2.x) * e[mi][ni][2],
                                       sigm(er[mi][ni][3] + br2.y) * e[mi][ni][3]);
                        }
                }
                if (do_head) {
                    float e2[2][2][4];
                    epi3<2>(sm, sbase, PARK_HI, PARK_LO, 128, 72,
                            g_Whi + ep.w2, g_Wlo + ep.w2, 64, tid, lane, m0w, wn * 16, e2);
                    #pragma unroll
                    for (int mi = 0; mi < 2; mi++)
                        #pragma unroll
                        for (int ni = 0; ni < 2; ni++) {
                            int c = wn * 16 + ni * 8 + t4 * 2;
                            float2 bv = *(const float2*)(ep.b2 + c);
                            int r0 = gr0 + m0w + mi * 16 + g4;
                            size_t o0 = ((size_t)(z * (TT - 1) + ep.t - 1) * NN + r0) * DIN + c;
                            size_t o1 = o0 + (size_t)8 * DIN;
                            *(float2*)(ep.dout + o0) =
                                make_float2(e2[mi][ni][0] + bv.x, e2[mi][ni][1] + bv.y);
                            *(float2*)(ep.dout + o1) =
                                make_float2(e2[mi][ni][2] + bv.x, e2[mi][ni][3] + bv.y);
                        }
                }
            }
        } else {                             // emode 4: H = blend
            frag2act<4>(acc, sm, ACT_HI, ACT_LO, 64, m0w, n0w, lane);
            const bf16* axh = g_AXhi + ((size_t)(ep.t * BB + z) * NN + gr0) * DIN;
            const bf16* axl = g_AXlo + ((size_t)(ep.t * BB + z) * NN + gr0) * DIN;
            #pragma unroll
            for (int it = 0; it < 2; it++) {
                int item = tid + it * 256, r = item >> 3, c = (item & 7) * 8;
                *(uint4*)(sm + ACT_HI + (size_t)r * AP2 + c) =
                    *(const uint4*)(axh + (size_t)r * DIN + c);
                *(uint4*)(sm + ACT_LO + (size_t)r * AP2 + c) =
                    *(const uint4*)(axl + (size_t)r * DIN + c);
            }
            float e[2][4][4];
            epi3<4>(sm, sbase, ACT_HI, ACT_LO, 192, 136,
                    g_Whi + ep.w1, g_Wlo + ep.w1, 128, tid, lane, m0w, n0e, e);
            const float ob = g_OBS[ep.t * BB + z];
            #pragma unroll
            for (int mi = 0; mi < 2; mi++)
                #pragma unroll
                for (int ni = 0; ni < 4; ni++) {
                    int c = n0e + ni * 8 + t4 * 2;
                    float2 bv = *(const float2*)(ep.b1 + c);
                    size_t i0 = ((size_t)z * NN + gr0 + m0w + mi * 16 + g4) * DR + c;
                    size_t i1 = i0 + (size_t)8 * DR;
                    float2 zz0 = *(const float2*)(g_Z + i0);
                    float2 zz1 = *(const float2*)(g_Z + i1);
                    float2 h0 = *(const float2*)(g_HV1 + i0);
                    float2 h1 = *(const float2*)(g_HV1 + i1);
                    float c0 = ftanh(e[mi][ni][0] + bv.x);
                    float c1 = ftanh(e[mi][ni][1] + bv.y);
                    float c2 = ftanh(e[mi][ni][2] + bv.x);
                    float c3 = ftanh(e[mi][ni][3] + bv.y);
                    float o0 = h0.x + (zz0.x * (c0 - h0.x)) * ob;
                    float o1 = h0.y + (zz0.y * (c1 - h0.y)) * ob;
                    float o2 = h1.x + (zz1.x * (c2 - h1.x)) * ob;
                    float o3 = h1.y + (zz1.y * (c3 - h1.y)) * ob;
                    *(float2*)(ep.of32 + i0) = make_float2(o0, o1);
                    *(float2*)(ep.of32 + i1) = make_float2(o2, o3);
                    store_hilo(ep.ohi, ep.olo, i0, o0, o1);
                    store_hilo(ep.ohi, ep.olo, i1, o2, o3);
                }
        }
    }
}

// --------------------------- small utility kernels -------------------------
__global__ void __launch_bounds__(256) convA_kernel(const float* __restrict__ A)
{
    const size_t r = blockIdx.x;
    const float* src = A + r * NN;
    bf16* dhi = g_Ahi + r * NN;
    bf16* dlo = g_Alo + r * NN;
    int i = threadIdx.x * 4;
    float4 v = *(const float4*)(src + i);
    float vv[4] = {v.x, v.y, v.z, v.w};
    #pragma unroll
    for (int j = 0; j < 4; j++) {
        bf16 h = __float2bfloat16(vv[j]);
        dhi[i+j] = h;
        dlo[i+j] = __float2bfloat16(vv[j] - __bfloat162float(h));
    }
}

__global__ void __launch_bounds__(256) convWall_kernel(
    const float* W0, const float* W1, const float* Wou, const float* Wz,
    const float* Wr, const float* Wh, const float* Wo)
{
    const float* W; long off; int n;
    switch (blockIdx.y) {
        case 0: W = W0;  off = OW0;   n = 16384; break;
        case 1: W = W1;  off = OW1;   n = 16384; break;
        case 2: W = Wou; off = OWOUT; n = 16384; break;
        case 3: W = Wz;  off = OWZ;   n = 24576; break;
        case 4: W = Wr;  off = OWR;   n = 24576; break;
        case 5: W = Wh;  off = OWH;   n = 24576; break;
        default: W = Wo; off = OWO;   n = 8192;  break;
    }
    int i = blockIdx.x * 256 + threadIdx.x;
    if (i >= n) return;
    float v = W[i];
    bf16 h = __float2bfloat16(v);
    g_Whi[off + i] = h;
    g_Wlo[off + i] = __float2bfloat16(v - __bfloat162float(h));
}

__global__ void __launch_bounds__(256) xmask_kernel(
    const float4* __restrict__ v, const float4* __restrict__ m)
{
    int i = blockIdx.x * 256 + threadIdx.x;
    float4 a = v[i], b = m[i];
    float x[4] = {a.x*b.x, a.y*b.y, a.z*b.z, a.w*b.w};
    bf16 hi[4], lo[4];
    #pragma unroll
    for (int j = 0; j < 4; j++) {
        hi[j] = __float2bfloat16(x[j]);
        lo[j] = __float2bfloat16(x[j] - __bfloat162float(hi[j]));
    }
    *(uint2*)&g_Xhi[(size_t)i*4] = *(uint2*)hi;
    *(uint2*)&g_Xlo[(size_t)i*4] = *(uint2*)lo;
}

__global__ void __launch_bounds__(256) inith_kernel(const float* __restrict__ h0)
{
    int i = blockIdx.x * 256 + threadIdx.x;
    float v = h0[i & (DR - 1)];
    g_H[i] = v;
    bf16 h = __float2bfloat16(v);
    g_Hhi[i] = h;
    g_Hlo[i] = __float2bfloat16(v - __bfloat162float(h));
}

__global__ void __launch_bounds__(256) obs_kernel(const float* __restrict__ masks)
{
    __shared__ float sh[256];
    int bt = blockIdx.x;
    const float* p = masks + (size_t)bt * (NN * DIN);
    float s = 0.f;
    for (int i = threadIdx.x; i < NN * DIN; i += 256) s += fabsf(p[i]);
    sh[threadIdx.x] = s; __syncthreads();
    for (int o = 128; o > 0; o >>= 1) {
        if (threadIdx.x < o) sh[threadIdx.x] += sh[threadIdx.x + o];
        __syncthreads();
    }
    if (threadIdx.x == 0) {
        int b = bt >> 5, t = bt & 31;
        g_OBS[t * BB + b] = (sh[0] > 1e-4f) ? 1.f : 0.f;
    }
}

// ------------------------------- launch ------------------------------------
extern "C" void kernel_launch(void* const* d_in, const int* in_sizes, int n_in,
                              void* d_out, int out_size)
{
    const float* values = (const float*)d_in[0];
    const float* masks  = (const float*)d_in[1];
    const float* A      = (const float*)d_in[2];
    const float* h0     = (const float*)d_in[3];
    const float* W0  = (const float*)d_in[4];  const float* b0v = (const float*)d_in[5];
    const float* W1  = (const float*)d_in[6];  const float* b1v = (const float*)d_in[7];
    const float* Wou = (const float*)d_in[8];  const float* bou = (const float*)d_in[9];
    const float* Wz  = (const float*)d_in[10]; const float* bz  = (const float*)d_in[11];
    const float* Wr  = (const float*)d_in[12]; const float* br  = (const float*)d_in[13];
    const float* Wh  = (const float*)d_in[14]; const float* bh  = (const float*)d_in[15];
    const float* Wo  = (const float*)d_in[16]; const float* bo  = (const float*)d_in[17];
    float* out = (float*)d_out;

    float *H, *HV1, *G1, *Z;
    bf16 *Xhi, *Xlo, *Hhi, *Hlo, *Uhi, *Ulo, *RHhi, *RHlo;
    cudaGetSymbolAddress((void**)&H,    g_H);
    cudaGetSymbolAddress((void**)&HV1,  g_HV1);
    cudaGetSymbolAddress((void**)&G1,   g_G1);
    cudaGetSymbolAddress((void**)&Z,    g_Z);
    cudaGetSymbolAddress((void**)&Xhi,  g_Xhi);  cudaGetSymbolAddress((void**)&Xlo,  g_Xlo);
    cudaGetSymbolAddress((void**)&Hhi,  g_Hhi);  cudaGetSymbolAddress((void**)&Hlo,  g_Hlo);
    cudaGetSymbolAddress((void**)&Uhi,  g_Uhi);  cudaGetSymbolAddress((void**)&Ulo,  g_Ulo);
    cudaGetSymbolAddress((void**)&RHhi, g_RHhi); cudaGetSymbolAddress((void**)&RHlo, g_RHlo);

    const int SM128 = 172032;                          // max(mainloop 159744, epi)
    const int SM64  = 3 * (2*64*72 + 2*64*72) * 2;     // 110592 B
    cudaFuncSetAttribute(agT_kernel<128>, cudaFuncAttributeMaxDynamicSharedMemorySize, SM128);
    cudaFuncSetAttribute(agT_kernel<64>,  cudaFuncAttributeMaxDynamicSharedMemorySize, SM64);

    // --- precompute ---
    convA_kernel<<<BB*NN, 256>>>(A);
    convWall_kernel<<<dim3(96, 7), 256>>>(W0, W1, Wou, Wz, Wr, Wh, Wo);
    xmask_kernel<<<(BB*TT*NN*DIN)/4/256, 256>>>(
        (const float4*)values, (const float4*)masks);
    obs_kernel<<<BB*TT, 256>>>(masks);
    inith_kernel<<<(BB*NN*DR)/256, 256>>>(h0);

    cudaLaunchAttribute pdlAttr[1];
    pdlAttr[0].id = cudaLaunchAttributeProgrammaticStreamSerialization;
    pdlAttr[0].val.programmaticStreamSerializationAllowed = 1;

    EpiArgs ax{0, 0, 0, 0, 0, 0, nullptr, nullptr, nullptr, nullptr,
               nullptr, nullptr, nullptr, nullptr, nullptr, nullptr, nullptr, nullptr};
    {
        cudaLaunchConfig_t cfg = {};
        cfg.gridDim = dim3(16, 1, BB*TT);
        cfg.blockDim = dim3(256, 1, 1);
        cfg.dynamicSmemBytes = SM64;
        cfg.stream = 0;
        cfg.attrs = pdlAttr;
        cfg.numAttrs = 1;
        cudaLaunchKernelEx(&cfg, agT_kernel<DIN>, (const bf16*)Xhi, (const bf16*)Xlo, TT, 1, ax);
    }

    auto AGE = [&](const bf16* bhi, const bf16* blo, EpiArgs ep) {
        cudaLaunchConfig_t cfg = {};
        cfg.gridDim = dim3(16, 1, BB);
        cfg.blockDim = dim3(256, 1, 1);
        cfg.dynamicSmemBytes = SM128;
        cfg.stream = 0;
        cfg.attrs = pdlAttr;
        cfg.numAttrs = 1;
        cudaLaunchKernelEx(&cfg, agT_kernel<DR>, bhi, blo, 1, 0, ep);
    };

    auto ODE = [&](int t) {
        bool gates = (t >= 0 && t < TT - 1);
        bool head  = (t >= 1);
        float* tf  = (t < 0) ? H : HV1;
        bf16* thi  = (t < 0) ? Hhi : nullptr;
        bf16* tlo  = (t < 0) ? Hlo : nullptr;
        AGE(Hhi, Hlo, {1, t, OW0, 0, 0, 0, b0v, nullptr, nullptr, nullptr,
                       nullptr, G1, nullptr, nullptr, Uhi, Ulo, nullptr, nullptr});
        AGE(Uhi, Ulo, {1, t, OW1, 0, 0, 0, b1v, nullptr, nullptr, nullptr,
                       nullptr, nullptr, nullptr, nullptr, Uhi, Ulo, nullptr, nullptr});
        AGE(Uhi, Ulo, {2, t, OWOUT, OWO, OWZ, OWR, bou, bo, bz, br,
                       tf, G1, gates ? Z : nullptr, head ? out : nullptr,
                       thi, tlo, RHhi, RHlo});
    };

    ODE(-1);

    for (int t = 0; t < TT; t++) {
        ODE(t);
        if (t < TT - 1)
            AGE(RHhi, RHlo, {4, t, OWH, 0, 0, 0, bh, nullptr, nullptr, nullptr,
                             H, nullptr, nullptr, nullptr, Hhi, Hlo, nullptr, nullptr});
    }
}